// round 11
// baseline (speedup 1.0000x reference)
#include <cuda_runtime.h>
#include <cuda_bf16.h>
#include <math.h>
#include <stdint.h>
#include <stddef.h>

// Problem constants (fixed by the dataset)
#define NN 50000
#define NE 800000
#define DIN 512
#define C1 256
#define C2 128
#define HID 64

// ---------------- scratch (device globals; no allocations allowed) ----------
__device__ float g_app_s[NN];
__device__ float g_app_d[NN];
__device__ float g_geo_s[NN];
__device__ float g_geo_d[NN];
__device__ float g_ew1[NE];
__device__ float g_deg1[NN];   // deg, then overwritten with dinv
__device__ float g_ms[NN];
__device__ float g_md[NN];
__device__ float g_ew2[NE];
__device__ float g_deg2[NN];
__device__ float g_h1[(size_t)NN * C1];
__device__ float g_out1[(size_t)NN * C1];   // pre-bias GCN1 accumulator
__device__ float g_h2[(size_t)NN * C2];
__device__ float g_out2[(size_t)NN * C2];
__device__ float g_proj[(size_t)NN * HID];
__device__ float g_wt1[(size_t)C1 * DIN];   // W_c1^T  [N=256][K=512]
__device__ float g_wt2[(size_t)C2 * C1];    // W_c2^T  [N=128][K=256]

// ---------------- helpers ----------------------------------------------------
__device__ __forceinline__ void redAdd4(float* addr, float4 v) {
    asm volatile("red.global.add.v4.f32 [%0], {%1,%2,%3,%4};"
                 :: "l"(addr), "f"(v.x), "f"(v.y), "f"(v.z), "f"(v.w)
                 : "memory");
}

__device__ __forceinline__ float warpReduceSum(float v) {
#pragma unroll
    for (int off = 16; off > 0; off >>= 1)
        v += __shfl_down_sync(0xFFFFFFFFu, v, off);
    return v;
}

__device__ __forceinline__ void mma_tf32(float* c, const uint32_t* a, const uint32_t* b) {
    asm volatile(
        "mma.sync.aligned.m16n8k8.row.col.f32.tf32.tf32.f32 "
        "{%0,%1,%2,%3}, {%4,%5,%6,%7}, {%8,%9}, {%0,%1,%2,%3};"
        : "+f"(c[0]), "+f"(c[1]), "+f"(c[2]), "+f"(c[3])
        : "r"(a[0]), "r"(a[1]), "r"(a[2]), "r"(a[3]), "r"(b[0]), "r"(b[1]));
}

// ldmatrix x4 on f32 data viewed as b16 pairs: thread t of matrix j gets
// (row t/4, f32-col t%4) -- exactly the mma tf32 fragment distribution.
#define LDSM_X4(r0, r1, r2, r3, addr) \
    asm volatile("ldmatrix.sync.aligned.m8n8.x4.shared.b16 {%0,%1,%2,%3}, [%4];" \
                 : "=r"(r0), "=r"(r1), "=r"(r2), "=r"(r3) : "r"(addr))

#define CP_ASYNC16(dst, src) \
    asm volatile("cp.async.cg.shared.global [%0], [%1], 16;" :: "r"(dst), "l"(src))
#define CP_COMMIT asm volatile("cp.async.commit_group;")
template <int N>
__device__ __forceinline__ void cp_wait() {
    asm volatile("cp.async.wait_group %0;" :: "n"(N));
}

// ---------------- kernels ----------------------------------------------------

// tiled transpose: Wt[n*K + k] = W[k*N + n]. K,N multiples of 32.
__global__ void k_transpose(const float* __restrict__ W, float* __restrict__ Wt,
                            int K, int N) {
    __shared__ float tile[32][33];
    int k0 = blockIdx.x * 32, n0 = blockIdx.y * 32;
    int tx = threadIdx.x & 31, ty = threadIdx.x >> 5;   // 32x8
#pragma unroll
    for (int i = ty; i < 32; i += 8)
        tile[i][tx] = W[(size_t)(k0 + i) * N + n0 + tx];
    __syncthreads();
#pragma unroll
    for (int i = ty; i < 32; i += 8)
        Wt[(size_t)(n0 + i) * K + k0 + tx] = tile[tx][i];
}

// node dots + zero both degree accumulators (fused)
__global__ void k_node_dots(const float* __restrict__ x,
                            const float* __restrict__ coords,
                            const float* __restrict__ Wapp,
                            const float* __restrict__ Wgeom) {
    int gw = (blockIdx.x * blockDim.x + threadIdx.x) >> 5;
    int lane = threadIdx.x & 31;
    if (gw >= NN) return;
    const float4* row = (const float4*)(x + (size_t)gw * DIN);
    const float4* wa = (const float4*)Wapp;
    float s = 0.f, d = 0.f;
#pragma unroll
    for (int i = 0; i < 4; i++) {
        int idx = lane + 32 * i;
        float4 v = row[idx];
        float4 ws = wa[idx];
        float4 wd = wa[idx + 128];
        s += v.x * ws.x + v.y * ws.y + v.z * ws.z + v.w * ws.w;
        d += v.x * wd.x + v.y * wd.y + v.z * wd.z + v.w * wd.w;
    }
    s = warpReduceSum(s);
    d = warpReduceSum(d);
    if (lane == 0) {
        g_app_s[gw] = s;
        g_app_d[gw] = d;
        float4 c = ((const float4*)coords)[gw];
        g_geo_s[gw] = c.x * Wgeom[0] + c.y * Wgeom[1] + c.z * Wgeom[2] + c.w * Wgeom[3];
        g_geo_d[gw] = c.x * Wgeom[4] + c.y * Wgeom[5] + c.z * Wgeom[6] + c.w * Wgeom[7];
        g_deg1[gw] = 0.f;
        g_deg2[gw] = 0.f;
    }
}

// edge weights for GCN1 + degree accumulation
__global__ void k_edge1(const int* __restrict__ src, const int* __restrict__ dst,
                        const float* __restrict__ Waff,
                        const float* __restrict__ bapp,
                        const float* __restrict__ bgeom,
                        const float* __restrict__ baff) {
    int e = blockIdx.x * blockDim.x + threadIdx.x;
    if (e >= NE) return;
    int s = src[e], d = dst[e];
    float x1 = fmaxf(g_app_s[s] + g_app_d[d] + bapp[0], 0.f);
    float x2 = fmaxf(g_geo_s[s] + g_geo_d[d] + bgeom[0], 0.f);
    float ew = fmaxf(x1 * Waff[0] + x2 * Waff[1] + baff[0], 0.f);
    g_ew1[e] = ew;
    if (ew != 0.f) atomicAdd(&g_deg1[d], ew);
}

__global__ void k_dinv1() {
    int i = blockIdx.x * blockDim.x + threadIdx.x;
    if (i < NN) g_deg1[i] = rsqrtf(g_deg1[i] + 1.0f);  // +1 self-loop; deg>=1
}

__global__ void k_dinv2() {
    int i = blockIdx.x * blockDim.x + threadIdx.x;
    if (i < NN) g_deg2[i] = rsqrtf(g_deg2[i] + 1.0f);
}

// ---------------- TF32 tensor-core GEMM (ldmatrix operands) -------------------
// C[M,N] = A[M,K] @ Bt[N,K]^T. Both operand tiles [128 x 16] K-major in smem,
// stride 20 floats (80B): LDSM row addresses hit banks 20r%32 -> conflict-free.
// Fragments via ldmatrix.m8n8.x4.b16 (f32 seen as b16 pairs).
// MODE bit0: relu(a + biasA[k]) applied to A fragments in registers.
// MODE bit1: also write Cs[r,:] = dinv[r]^2 * C[r,:].
#define GA_BM 128
#define GA_BK 16
#define GA_STRIDE 20

template <int MODE>
__global__ __launch_bounds__(256) void k_gemm_tf32(
    const float* __restrict__ A, const float* __restrict__ Bt,
    float* __restrict__ C, int M, int N, int K,
    const float* __restrict__ biasA,
    float* __restrict__ Cs, const float* __restrict__ dinv) {
    __shared__ __align__(16) float As[2][GA_BM * GA_STRIDE];
    __shared__ __align__(16) float Bs[2][GA_BM * GA_STRIDE];

    const int tid = threadIdx.x;
    const int lane = tid & 31;
    const int wid = tid >> 5;
    const int wm = wid & 3;       // 0..3  (warp row)
    const int wn = wid >> 2;      // 0..1  (warp col)
    const int qid = lane & 3;

    const int row0 = blockIdx.x * GA_BM;
    const int col0 = blockIdx.y * 128;

    // staging: 128 rows x 16 floats per tile, 2 x 16B chunks per thread per tile
    const int sr0 = tid >> 2;               // 0..63
    const int sc = (tid & 3) * 4;           // 0,4,8,12
    const int arow_g0 = min(row0 + sr0, M - 1);
    const int arow_g1 = min(row0 + sr0 + 64, M - 1);
    const int brow_g0 = col0 + sr0;         // < N by construction
    const int brow_g1 = col0 + sr0 + 64;

    // LDSM per-thread row/col selectors
    const int a_row = ((lane >> 3) & 1) * 8 + (lane & 7);  // matrices {r,r+8,r,r+8}
    const int a_koff = (lane >> 4) * 4;                    // matrices {k,k,k+4,k+4}
    const int b_row = (lane >> 4) * 8 + (lane & 7);        // matrices {n,n,n+8,n+8}
    const int b_koff = ((lane >> 3) & 1) * 4;              // matrices {k,k+4,k,k+4}

    float acc[2][8][4];
#pragma unroll
    for (int mt = 0; mt < 2; mt++)
#pragma unroll
        for (int nt = 0; nt < 8; nt++)
#pragma unroll
            for (int i = 0; i < 4; i++) acc[mt][nt][i] = 0.f;

    auto load_tile = [&](int buf, int k0) {
        uint32_t a_s0 = (uint32_t)__cvta_generic_to_shared(
            &As[buf][sr0 * GA_STRIDE + sc]);
        uint32_t a_s1 = (uint32_t)__cvta_generic_to_shared(
            &As[buf][(sr0 + 64) * GA_STRIDE + sc]);
        CP_ASYNC16(a_s0, A + (size_t)arow_g0 * K + k0 + sc);
        CP_ASYNC16(a_s1, A + (size_t)arow_g1 * K + k0 + sc);
        uint32_t b_s0 = (uint32_t)__cvta_generic_to_shared(
            &Bs[buf][sr0 * GA_STRIDE + sc]);
        uint32_t b_s1 = (uint32_t)__cvta_generic_to_shared(
            &Bs[buf][(sr0 + 64) * GA_STRIDE + sc]);
        CP_ASYNC16(b_s0, Bt + (size_t)brow_g0 * K + k0 + sc);
        CP_ASYNC16(b_s1, Bt + (size_t)brow_g1 * K + k0 + sc);
    };

    const int ntiles = K / GA_BK;
    load_tile(0, 0);
    CP_COMMIT;

    int buf = 0;
    for (int t = 0; t < ntiles; t++) {
        const int k0 = t * GA_BK;
        if (t + 1 < ntiles) {
            load_tile(buf ^ 1, (t + 1) * GA_BK);
            CP_COMMIT;
            cp_wait<1>();
        } else {
            cp_wait<0>();
        }
        __syncthreads();

        const float* as = As[buf];
        const float* bs = Bs[buf];
#pragma unroll
        for (int ks = 0; ks < 2; ks++) {
            uint32_t a[2][4];
#pragma unroll
            for (int mt = 0; mt < 2; mt++) {
                uint32_t addr = (uint32_t)__cvta_generic_to_shared(
                    &as[(wm * 32 + mt * 16 + a_row) * GA_STRIDE + ks * 8 + a_koff]);
                LDSM_X4(a[mt][0], a[mt][1], a[mt][2], a[mt][3], addr);
            }
            if (MODE & 1) {
                const int kk = k0 + ks * 8 + qid;
                float ab0 = biasA[kk];
                float ab1 = biasA[kk + 4];
#pragma unroll
                for (int mt = 0; mt < 2; mt++) {
                    a[mt][0] = __float_as_uint(fmaxf(__uint_as_float(a[mt][0]) + ab0, 0.f));
                    a[mt][1] = __float_as_uint(fmaxf(__uint_as_float(a[mt][1]) + ab0, 0.f));
                    a[mt][2] = __float_as_uint(fmaxf(__uint_as_float(a[mt][2]) + ab1, 0.f));
                    a[mt][3] = __float_as_uint(fmaxf(__uint_as_float(a[mt][3]) + ab1, 0.f));
                }
            }
            uint32_t b[4][4];
#pragma unroll
            for (int ntp = 0; ntp < 4; ntp++) {
                uint32_t addr = (uint32_t)__cvta_generic_to_shared(
                    &bs[(wn * 64 + ntp * 16 + b_row) * GA_STRIDE + ks * 8 + b_koff]);
                LDSM_X4(b[ntp][0], b[ntp][1], b[ntp][2], b[ntp][3], addr);
            }
#pragma unroll
            for (int ntp = 0; ntp < 4; ntp++) {
                mma_tf32(acc[0][2 * ntp],     a[0], &b[ntp][0]);
                mma_tf32(acc[1][2 * ntp],     a[1], &b[ntp][0]);
                mma_tf32(acc[0][2 * ntp + 1], a[0], &b[ntp][2]);
                mma_tf32(acc[1][2 * ntp + 1], a[1], &b[ntp][2]);
            }
        }
        __syncthreads();
        buf ^= 1;
    }

    // epilogue: write h (C) and optionally dinv^2-scaled self-loop term (Cs)
    const int grp = lane >> 2;
#pragma unroll
    for (int mt = 0; mt < 2; mt++) {
        int r = row0 + wm * 32 + mt * 16 + grp;
        float c0 = 0.f, c8 = 0.f;
        if (MODE & 2) {
            if (r < M)     { float d0 = dinv[r];     c0 = d0 * d0; }
            if (r + 8 < M) { float d8 = dinv[r + 8]; c8 = d8 * d8; }
        }
#pragma unroll
        for (int nt = 0; nt < 8; nt++) {
            int c = col0 + wn * 64 + nt * 8 + qid * 2;
            if (r < M) {
                float2 v = make_float2(acc[mt][nt][0], acc[mt][nt][1]);
                *(float2*)(C + (size_t)r * N + c) = v;
                if (MODE & 2) {
                    float2 sv = make_float2(c0 * v.x, c0 * v.y);
                    *(float2*)(Cs + (size_t)r * N + c) = sv;
                }
            }
            if (r + 8 < M) {
                float2 v = make_float2(acc[mt][nt][2], acc[mt][nt][3]);
                *(float2*)(C + (size_t)(r + 8) * N + c) = v;
                if (MODE & 2) {
                    float2 sv = make_float2(c8 * v.x, c8 * v.y);
                    *(float2*)(Cs + (size_t)(r + 8) * N + c) = sv;
                }
            }
        }
    }
}

// per-edge scatter-add (256-dim), warp per edge, float4 red atomics
__global__ void k_scatter1(const int* __restrict__ src, const int* __restrict__ dst) {
    int e = (blockIdx.x * blockDim.x + threadIdx.x) >> 5;
    if (e >= NE) return;
    float ew = g_ew1[e];
    if (ew == 0.f) return;
    int lane = threadIdx.x & 31;
    int s = src[e], d = dst[e];
    float coef = g_deg1[s] * ew * g_deg1[d];
    const float4* hs = (const float4*)(g_h1 + (size_t)s * C1);
    float* od = g_out1 + (size_t)d * C1;
#pragma unroll
    for (int i = 0; i < 2; i++) {
        int idx = lane + 32 * i;
        float4 v = hs[idx];
        redAdd4(od + idx * 4, make_float4(coef * v.x, coef * v.y, coef * v.z, coef * v.w));
    }
}

// m_s / m_d dots over relu(out1 + b_c1), warp per node (bias+relu inline)
__global__ void k_mdots(const float* __restrict__ Wm1, const float* __restrict__ bc1) {
    int gw = (blockIdx.x * blockDim.x + threadIdx.x) >> 5;
    int lane = threadIdx.x & 31;
    if (gw >= NN) return;
    const float4* row = (const float4*)(g_out1 + (size_t)gw * C1);
    const float4* wm = (const float4*)Wm1;
    const float4* bb = (const float4*)bc1;
    float s = 0.f, d = 0.f;
#pragma unroll
    for (int i = 0; i < 2; i++) {
        int idx = lane + 32 * i;
        float4 v = row[idx];
        float4 b = bb[idx];
        v.x = fmaxf(v.x + b.x, 0.f);
        v.y = fmaxf(v.y + b.y, 0.f);
        v.z = fmaxf(v.z + b.z, 0.f);
        v.w = fmaxf(v.w + b.w, 0.f);
        float4 ws = wm[idx];
        float4 wd = wm[idx + 64];
        s += v.x * ws.x + v.y * ws.y + v.z * ws.z + v.w * ws.w;
        d += v.x * wd.x + v.y * wd.y + v.z * wd.z + v.w * wd.w;
    }
    s = warpReduceSum(s);
    d = warpReduceSum(d);
    if (lane == 0) { g_ms[gw] = s; g_md[gw] = d; }
}

__global__ void k_edge2(const int* __restrict__ src, const int* __restrict__ dst,
                        const float* __restrict__ bm1) {
    int e = blockIdx.x * blockDim.x + threadIdx.x;
    if (e >= NE) return;
    int s = src[e], d = dst[e];
    float ea = fmaxf(g_ms[s] + g_md[d] + bm1[0], 0.f);
    g_ew2[e] = ea;
    if (ea != 0.f) atomicAdd(&g_deg2[d], ea);
}

__global__ void k_scatter2(const int* __restrict__ src, const int* __restrict__ dst) {
    int e = (blockIdx.x * blockDim.x + threadIdx.x) >> 5;
    if (e >= NE) return;
    float ew = g_ew2[e];
    if (ew == 0.f) return;
    int lane = threadIdx.x & 31;
    int s = src[e], d = dst[e];
    float coef = g_deg2[s] * ew * g_deg2[d];
    const float4* hs = (const float4*)(g_h2 + (size_t)s * C2);
    float* od = g_out2 + (size_t)d * C2;
    float4 v = hs[lane];
    redAdd4(od + lane * 4, make_float4(coef * v.x, coef * v.y, coef * v.z, coef * v.w));
}

// proj = out2 @ W_f1  ([N,128]x[128,64]); b_c2 cancels in the pairwise diff so skipped
__global__ void k_proj(const float* __restrict__ Wf1) {
    __shared__ float W1s[C2 * HID];
    for (int i = threadIdx.x; i < C2 * HID; i += blockDim.x) W1s[i] = Wf1[i];
    __syncthreads();
    int t = blockIdx.x * blockDim.x + threadIdx.x;
    int node = t >> 6;
    int j = t & 63;
    if (node >= NN) return;
    const float* row = g_out2 + (size_t)node * C2;
    float acc = 0.f;
#pragma unroll 8
    for (int k = 0; k < C2; k++) acc = fmaf(row[k], W1s[k * HID + j], acc);
    g_proj[(size_t)node * HID + j] = acc;
}

// final: sigmoid( relu(proj[a]-proj[b]+b_f1) @ W_f2 + b_f2 )
// half-warp (16 lanes) per edge, float4 loads (16*4 = 64 = HID)
__global__ void k_final(const int* __restrict__ ea, const int* __restrict__ eb,
                        const float* __restrict__ bf1, const float* __restrict__ Wf2,
                        const float* __restrict__ bf2, float* __restrict__ out) {
    int t = blockIdx.x * blockDim.x + threadIdx.x;
    int e = t >> 4;
    if (e >= NE) return;
    int l16 = t & 15;
    int a = ea[e], b = eb[e];
    float4 va = ((const float4*)(g_proj + (size_t)a * HID))[l16];
    float4 vb = ((const float4*)(g_proj + (size_t)b * HID))[l16];
    float4 bb = ((const float4*)bf1)[l16];
    float4 w  = ((const float4*)Wf2)[l16];
    float acc = fmaxf(va.x - vb.x + bb.x, 0.f) * w.x
              + fmaxf(va.y - vb.y + bb.y, 0.f) * w.y
              + fmaxf(va.z - vb.z + bb.z, 0.f) * w.z
              + fmaxf(va.w - vb.w + bb.w, 0.f) * w.w;
#pragma unroll
    for (int off = 8; off > 0; off >>= 1)
        acc += __shfl_down_sync(0xFFFFFFFFu, acc, off, 16);
    if (l16 == 0) {
        float z = acc + bf2[0];
        out[e] = 1.f / (1.f + expf(-z));
    }
}

// ---------------- launcher ---------------------------------------------------
extern "C" void kernel_launch(void* const* d_in, const int* in_sizes, int n_in,
                              void* d_out, int out_size) {
    const float* x      = (const float*)d_in[0];
    const float* coords = (const float*)d_in[1];
    const float* W_app  = (const float*)d_in[2];
    const float* b_app  = (const float*)d_in[3];
    const float* W_geom = (const float*)d_in[4];
    const float* b_geom = (const float*)d_in[5];
    const float* W_aff  = (const float*)d_in[6];
    const float* b_aff  = (const float*)d_in[7];
    const float* W_c1   = (const float*)d_in[8];
    const float* b_c1   = (const float*)d_in[9];
    const float* W_m1   = (const float*)d_in[10];
    const float* b_m1   = (const float*)d_in[11];
    const float* W_c2   = (const float*)d_in[12];
    // d_in[13] = b_c2 (cancels in pairwise diff; unused)
    const float* W_f1   = (const float*)d_in[14];
    const float* b_f1   = (const float*)d_in[15];
    const float* W_f2   = (const float*)d_in[16];
    const float* b_f2   = (const float*)d_in[17];
    const int* ei  = (const int*)d_in[18];
    const int* ei2 = (const int*)d_in[19];
    const int* src = ei;
    const int* dst = ei + NE;

    float *h1p, *out1p, *h2p, *out2p, *dinv1p, *dinv2p, *wt1p, *wt2p;
    cudaGetSymbolAddress((void**)&h1p, g_h1);
    cudaGetSymbolAddress((void**)&out1p, g_out1);
    cudaGetSymbolAddress((void**)&h2p, g_h2);
    cudaGetSymbolAddress((void**)&out2p, g_out2);
    cudaGetSymbolAddress((void**)&dinv1p, g_deg1);
    cudaGetSymbolAddress((void**)&dinv2p, g_deg2);
    cudaGetSymbolAddress((void**)&wt1p, g_wt1);
    cudaGetSymbolAddress((void**)&wt2p, g_wt2);

    // 0,1: weight transposes (K-major B operands for ldmatrix)
    k_transpose<<<dim3(DIN / 32, C1 / 32), 256>>>(W_c1, wt1p, DIN, C1);
    k_transpose<<<dim3(C1 / 32, C2 / 32), 256>>>(W_c2, wt2p, C1, C2);
    // 2
    k_node_dots<<<(NN + 7) / 8, 256>>>(x, coords, W_app, W_geom);
    // 3
    k_edge1<<<(NE + 255) / 256, 256>>>(src, dst, W_aff, b_app, b_geom, b_aff);
    // 4
    k_dinv1<<<(NN + 255) / 256, 256>>>();
    // 5: GEMM1 (h1 = x @ W_c1, + out1 = dinv1^2 * h1)
    k_gemm_tf32<2><<<dim3((NN + 127) / 128, C1 / 128), 256>>>(
        x, wt1p, h1p, NN, C1, DIN, nullptr, out1p, dinv1p);
    // 6
    k_scatter1<<<(NE * 32 + 255) / 256, 256>>>(src, dst);
    // 7
    k_mdots<<<(NN + 7) / 8, 256>>>(W_m1, b_c1);
    // 8
    k_edge2<<<(NE + 255) / 256, 256>>>(src, dst, b_m1);
    // 9
    k_dinv2<<<(NN + 255) / 256, 256>>>();
    // 10: GEMM2 (A = relu(out1 + b_c1) inline, h2 = A @ W_c2, + out2 = dinv2^2 * h2)
    k_gemm_tf32<3><<<dim3((NN + 127) / 128, C2 / 128), 256>>>(
        out1p, wt2p, h2p, NN, C2, C1, b_c1, out2p, dinv2p);
    // 11
    k_scatter2<<<(NE * 32 + 255) / 256, 256>>>(src, dst);
    // 12
    k_proj<<<(NN * HID + 511) / 512, 512>>>(W_f1);
    // 13
    k_final<<<(NE * 16 + 255) / 256, 256>>>(ei2, ei2 + NE, b_f1, W_f2, b_f2,
                                            (float*)d_out);
}

// round 13
// speedup vs baseline: 1.0551x; 1.0551x over previous
#include <cuda_runtime.h>
#include <cuda_bf16.h>
#include <math.h>
#include <stdint.h>
#include <stddef.h>

// Problem constants (fixed by the dataset)
#define NN 50000
#define NE 800000
#define DIN 512
#define C1 256
#define C2 128
#define HID 64

// ---------------- scratch (device globals; no allocations allowed) ----------
__device__ float g_app_s[NN];
__device__ float g_app_d[NN];
__device__ float g_geo_s[NN];
__device__ float g_geo_d[NN];
__device__ float g_ew1[NE];
__device__ float g_deg1[NN];   // deg, then overwritten with dinv
__device__ float g_ms[NN];
__device__ float g_md[NN];
__device__ float g_ew2[NE];
__device__ float g_deg2[NN];
__device__ float g_h1[(size_t)NN * C1];
__device__ float g_out1[(size_t)NN * C1];   // pre-bias GCN1 result
__device__ float g_h2[(size_t)NN * C2];
__device__ float g_out2[(size_t)NN * C2];
__device__ float g_proj[(size_t)NN * HID];
// dst-CSR (rebuilt every launch; shared by both GCN layers)
__device__ int  g_cnt[NN];      // per-dst edge count (all edges)
__device__ int  g_rowptr[NN];   // exclusive prefix of g_cnt
__device__ int  g_woff[NN];     // write cursors for placement
__device__ int2 g_csr[NE];      // {src, edge_id} per slot

// ---------------- helpers ----------------------------------------------------
__device__ __forceinline__ float warpReduceSum(float v) {
#pragma unroll
    for (int off = 16; off > 0; off >>= 1)
        v += __shfl_down_sync(0xFFFFFFFFu, v, off);
    return v;
}

// Raw f32 bits as tf32 operand (truncation; error budget has >5x margin).
__device__ __forceinline__ uint32_t f2tf(float f) {
    return __float_as_uint(f);
}

__device__ __forceinline__ void mma_tf32(float* c, const uint32_t* a, const uint32_t* b) {
    asm volatile(
        "mma.sync.aligned.m16n8k8.row.col.f32.tf32.tf32.f32 "
        "{%0,%1,%2,%3}, {%4,%5,%6,%7}, {%8,%9}, {%0,%1,%2,%3};"
        : "+f"(c[0]), "+f"(c[1]), "+f"(c[2]), "+f"(c[3])
        : "r"(a[0]), "r"(a[1]), "r"(a[2]), "r"(a[3]), "r"(b[0]), "r"(b[1]));
}

#define CP_ASYNC16(dst, src) \
    asm volatile("cp.async.cg.shared.global [%0], [%1], 16;" :: "r"(dst), "l"(src))
#define CP_COMMIT asm volatile("cp.async.commit_group;")
template <int N>
__device__ __forceinline__ void cp_wait() {
    asm volatile("cp.async.wait_group %0;" :: "n"(N));
}

// ---------------- kernels ----------------------------------------------------

// node dots + zero degree and CSR-count accumulators (fused)
__global__ void k_node_dots(const float* __restrict__ x,
                            const float* __restrict__ coords,
                            const float* __restrict__ Wapp,
                            const float* __restrict__ Wgeom) {
    int gw = (blockIdx.x * blockDim.x + threadIdx.x) >> 5;
    int lane = threadIdx.x & 31;
    if (gw >= NN) return;
    const float4* row = (const float4*)(x + (size_t)gw * DIN);
    const float4* wa = (const float4*)Wapp;
    float s = 0.f, d = 0.f;
#pragma unroll
    for (int i = 0; i < 4; i++) {
        int idx = lane + 32 * i;
        float4 v = row[idx];
        float4 ws = wa[idx];
        float4 wd = wa[idx + 128];
        s += v.x * ws.x + v.y * ws.y + v.z * ws.z + v.w * ws.w;
        d += v.x * wd.x + v.y * wd.y + v.z * wd.z + v.w * wd.w;
    }
    s = warpReduceSum(s);
    d = warpReduceSum(d);
    if (lane == 0) {
        g_app_s[gw] = s;
        g_app_d[gw] = d;
        float4 c = ((const float4*)coords)[gw];
        g_geo_s[gw] = c.x * Wgeom[0] + c.y * Wgeom[1] + c.z * Wgeom[2] + c.w * Wgeom[3];
        g_geo_d[gw] = c.x * Wgeom[4] + c.y * Wgeom[5] + c.z * Wgeom[6] + c.w * Wgeom[7];
        g_deg1[gw] = 0.f;
        g_deg2[gw] = 0.f;
        g_cnt[gw] = 0;
    }
}

// edge weights for GCN1 + degree + CSR histogram
__global__ void k_edge1(const int* __restrict__ src, const int* __restrict__ dst,
                        const float* __restrict__ Waff,
                        const float* __restrict__ bapp,
                        const float* __restrict__ bgeom,
                        const float* __restrict__ baff) {
    int e = blockIdx.x * blockDim.x + threadIdx.x;
    if (e >= NE) return;
    int s = src[e], d = dst[e];
    float x1 = fmaxf(g_app_s[s] + g_app_d[d] + bapp[0], 0.f);
    float x2 = fmaxf(g_geo_s[s] + g_geo_d[d] + bgeom[0], 0.f);
    float ew = fmaxf(x1 * Waff[0] + x2 * Waff[1] + baff[0], 0.f);
    g_ew1[e] = ew;
    if (ew != 0.f) atomicAdd(&g_deg1[d], ew);
    atomicAdd(&g_cnt[d], 1);
}

// exclusive prefix sum over g_cnt (single block, 1024 threads)
__global__ void k_scan() {
    __shared__ int part[1024];
    const int t = threadIdx.x;
    const int per = (NN + 1023) / 1024;   // 49
    const int base = t * per;
    int sum = 0;
    for (int i = 0; i < per; i++) {
        int idx = base + i;
        if (idx < NN) sum += g_cnt[idx];
    }
    part[t] = sum;
    __syncthreads();
    for (int off = 1; off < 1024; off <<= 1) {
        int v = (t >= off) ? part[t - off] : 0;
        __syncthreads();
        part[t] += v;
        __syncthreads();
    }
    int run = (t > 0) ? part[t - 1] : 0;
    for (int i = 0; i < per; i++) {
        int idx = base + i;
        if (idx < NN) {
            g_rowptr[idx] = run;
            g_woff[idx] = run;
            run += g_cnt[idx];
        }
    }
}

// place edges into CSR slots
__global__ void k_place(const int* __restrict__ src, const int* __restrict__ dst) {
    int e = blockIdx.x * blockDim.x + threadIdx.x;
    if (e >= NE) return;
    int d = dst[e];
    int pos = atomicAdd(&g_woff[d], 1);
    g_csr[pos] = make_int2(src[e], e);
}

__global__ void k_dinv1() {
    int i = blockIdx.x * blockDim.x + threadIdx.x;
    if (i < NN) g_deg1[i] = rsqrtf(g_deg1[i] + 1.0f);  // +1 self-loop; deg>=1
}

__global__ void k_dinv2() {
    int i = blockIdx.x * blockDim.x + threadIdx.x;
    if (i < NN) g_deg2[i] = rsqrtf(g_deg2[i] + 1.0f);
}

// ---------------- TF32 tensor-core GEMM --------------------------------------
// C[M,N] = A[M,K] @ B[K,N], row-major. Block tile 128x128x16, 8 warps,
// warp tile 32x64 via m16n8k8. cp.async double buffer.
// MODE bit0: apply relu(a + biasA[k]) to A fragments.
#define GA_BM 128
#define GA_BK 16
#define GA_AS_STRIDE 20
#define GA_BS_STRIDE 136

template <int MODE>
__global__ __launch_bounds__(256) void k_gemm_tf32(
    const float* __restrict__ A, const float* __restrict__ B,
    float* __restrict__ C, int M, int N, int K,
    const float* __restrict__ biasA) {
    __shared__ __align__(16) float As[2][GA_BM * GA_AS_STRIDE];
    __shared__ __align__(16) float Bs[2][GA_BK * GA_BS_STRIDE];

    const int tid = threadIdx.x;
    const int lane = tid & 31;
    const int wid = tid >> 5;
    const int wm = wid & 3;
    const int wn = wid >> 2;
    const int grp = lane >> 2;
    const int qid = lane & 3;

    const int row0 = blockIdx.x * GA_BM;
    const int col0 = blockIdx.y * 128;

    const int ar0 = tid >> 2;
    const int ac = (tid & 3) * 4;
    const int br0 = tid >> 5;
    const int bc = (tid & 31) * 4;

    const int arow_g0 = min(row0 + ar0, M - 1);
    const int arow_g1 = min(row0 + ar0 + 64, M - 1);

    float acc[2][8][4];
#pragma unroll
    for (int mt = 0; mt < 2; mt++)
#pragma unroll
        for (int nt = 0; nt < 8; nt++)
#pragma unroll
            for (int i = 0; i < 4; i++) acc[mt][nt][i] = 0.f;

    auto load_tile = [&](int buf, int k0) {
        uint32_t a_s0 = (uint32_t)__cvta_generic_to_shared(
            &As[buf][ar0 * GA_AS_STRIDE + ac]);
        uint32_t a_s1 = (uint32_t)__cvta_generic_to_shared(
            &As[buf][(ar0 + 64) * GA_AS_STRIDE + ac]);
        CP_ASYNC16(a_s0, A + (size_t)arow_g0 * K + k0 + ac);
        CP_ASYNC16(a_s1, A + (size_t)arow_g1 * K + k0 + ac);
        uint32_t b_s0 = (uint32_t)__cvta_generic_to_shared(
            &Bs[buf][br0 * GA_BS_STRIDE + bc]);
        uint32_t b_s1 = (uint32_t)__cvta_generic_to_shared(
            &Bs[buf][(br0 + 8) * GA_BS_STRIDE + bc]);
        CP_ASYNC16(b_s0, B + (size_t)(k0 + br0) * N + col0 + bc);
        CP_ASYNC16(b_s1, B + (size_t)(k0 + br0 + 8) * N + col0 + bc);
    };

    const int ntiles = K / GA_BK;
    load_tile(0, 0);
    CP_COMMIT;

    int buf = 0;
    const int arow_base = wm * 32 + grp;
    const int bcol_base = wn * 64 + grp;

    for (int t = 0; t < ntiles; t++) {
        const int k0 = t * GA_BK;
        if (t + 1 < ntiles) {
            load_tile(buf ^ 1, (t + 1) * GA_BK);
            CP_COMMIT;
            cp_wait<1>();
        } else {
            cp_wait<0>();
        }
        __syncthreads();

        const float* as = As[buf];
        const float* bs = Bs[buf];
#pragma unroll
        for (int ks = 0; ks < 2; ks++) {
            const int kk = ks * 8 + qid;
            float ab0 = 0.f, ab1 = 0.f;
            if (MODE & 1) {
                ab0 = biasA[k0 + kk];
                ab1 = biasA[k0 + kk + 4];
            }
            uint32_t a[2][4];
#pragma unroll
            for (int mt = 0; mt < 2; mt++) {
                const float* ap = as + (arow_base + mt * 16) * GA_AS_STRIDE + kk;
                float v0 = ap[0];
                float v1 = ap[8 * GA_AS_STRIDE];
                float v2 = ap[4];
                float v3 = ap[8 * GA_AS_STRIDE + 4];
                if (MODE & 1) {
                    v0 = fmaxf(v0 + ab0, 0.f);
                    v1 = fmaxf(v1 + ab0, 0.f);
                    v2 = fmaxf(v2 + ab1, 0.f);
                    v3 = fmaxf(v3 + ab1, 0.f);
                }
                a[mt][0] = f2tf(v0);
                a[mt][1] = f2tf(v1);
                a[mt][2] = f2tf(v2);
                a[mt][3] = f2tf(v3);
            }
            const float* bp = bs + kk * GA_BS_STRIDE + bcol_base;
#pragma unroll
            for (int nt = 0; nt < 8; nt++) {
                uint32_t b[2];
                b[0] = f2tf(bp[nt * 8]);
                b[1] = f2tf(bp[4 * GA_BS_STRIDE + nt * 8]);
                mma_tf32(acc[0][nt], a[0], b);
                mma_tf32(acc[1][nt], a[1], b);
            }
        }
        __syncthreads();
        buf ^= 1;
    }

#pragma unroll
    for (int mt = 0; mt < 2; mt++) {
        int r = row0 + wm * 32 + mt * 16 + grp;
#pragma unroll
        for (int nt = 0; nt < 8; nt++) {
            int c = col0 + wn * 64 + nt * 8 + qid * 2;
            if (r < M)
                *(float2*)(C + (size_t)r * N + c) =
                    make_float2(acc[mt][nt][0], acc[mt][nt][1]);
            if (r + 8 < M)
                *(float2*)(C + (size_t)(r + 8) * N + c) =
                    make_float2(acc[mt][nt][2], acc[mt][nt][3]);
        }
    }
}

// GCN1 aggregation: gather per dst node (warp per node). out1[d] =
// dinv1[d]^2*h1[d] + sum_e coef_e * h1[src_e].  256-dim: 2 float4/lane.
__global__ void k_gather1() {
    int node = (blockIdx.x * blockDim.x + threadIdx.x) >> 5;
    if (node >= NN) return;
    int lane = threadIdx.x & 31;
    int start = g_rowptr[node];
    int cnt = g_cnt[node];
    float di = g_deg1[node];
    const float4* hd = (const float4*)(g_h1 + (size_t)node * C1);
    float self = di * di;
    float4 v0 = hd[lane], v1 = hd[lane + 32];
    float4 acc0 = make_float4(self * v0.x, self * v0.y, self * v0.z, self * v0.w);
    float4 acc1 = make_float4(self * v1.x, self * v1.y, self * v1.z, self * v1.w);
    for (int i = 0; i < cnt; i++) {
        int2 se = g_csr[start + i];
        float ew = g_ew1[se.y];
        if (ew == 0.f) continue;
        float coef = g_deg1[se.x] * ew * di;
        const float4* hs = (const float4*)(g_h1 + (size_t)se.x * C1);
        float4 a = hs[lane], b = hs[lane + 32];
        acc0.x += coef * a.x; acc0.y += coef * a.y;
        acc0.z += coef * a.z; acc0.w += coef * a.w;
        acc1.x += coef * b.x; acc1.y += coef * b.y;
        acc1.z += coef * b.z; acc1.w += coef * b.w;
    }
    float4* od = (float4*)(g_out1 + (size_t)node * C1);
    od[lane] = acc0;
    od[lane + 32] = acc1;
}

// GCN2 aggregation: same, 128-dim: 1 float4/lane.
__global__ void k_gather2() {
    int node = (blockIdx.x * blockDim.x + threadIdx.x) >> 5;
    if (node >= NN) return;
    int lane = threadIdx.x & 31;
    int start = g_rowptr[node];
    int cnt = g_cnt[node];
    float di = g_deg2[node];
    const float4* hd = (const float4*)(g_h2 + (size_t)node * C2);
    float self = di * di;
    float4 v0 = hd[lane];
    float4 acc = make_float4(self * v0.x, self * v0.y, self * v0.z, self * v0.w);
    for (int i = 0; i < cnt; i++) {
        int2 se = g_csr[start + i];
        float ew = g_ew2[se.y];
        if (ew == 0.f) continue;
        float coef = g_deg2[se.x] * ew * di;
        const float4* hs = (const float4*)(g_h2 + (size_t)se.x * C2);
        float4 a = hs[lane];
        acc.x += coef * a.x; acc.y += coef * a.y;
        acc.z += coef * a.z; acc.w += coef * a.w;
    }
    ((float4*)(g_out2 + (size_t)node * C2))[lane] = acc;
}

// m_s / m_d dots over relu(out1 + b_c1), warp per node (bias+relu inline)
__global__ void k_mdots(const float* __restrict__ Wm1, const float* __restrict__ bc1) {
    int gw = (blockIdx.x * blockDim.x + threadIdx.x) >> 5;
    int lane = threadIdx.x & 31;
    if (gw >= NN) return;
    const float4* row = (const float4*)(g_out1 + (size_t)gw * C1);
    const float4* wm = (const float4*)Wm1;
    const float4* bb = (const float4*)bc1;
    float s = 0.f, d = 0.f;
#pragma unroll
    for (int i = 0; i < 2; i++) {
        int idx = lane + 32 * i;
        float4 v = row[idx];
        float4 b = bb[idx];
        v.x = fmaxf(v.x + b.x, 0.f);
        v.y = fmaxf(v.y + b.y, 0.f);
        v.z = fmaxf(v.z + b.z, 0.f);
        v.w = fmaxf(v.w + b.w, 0.f);
        float4 ws = wm[idx];
        float4 wd = wm[idx + 64];
        s += v.x * ws.x + v.y * ws.y + v.z * ws.z + v.w * ws.w;
        d += v.x * wd.x + v.y * wd.y + v.z * wd.z + v.w * wd.w;
    }
    s = warpReduceSum(s);
    d = warpReduceSum(d);
    if (lane == 0) { g_ms[gw] = s; g_md[gw] = d; }
}

__global__ void k_edge2(const int* __restrict__ src, const int* __restrict__ dst,
                        const float* __restrict__ bm1) {
    int e = blockIdx.x * blockDim.x + threadIdx.x;
    if (e >= NE) return;
    int s = src[e], d = dst[e];
    float ea = fmaxf(g_ms[s] + g_md[d] + bm1[0], 0.f);
    g_ew2[e] = ea;
    if (ea != 0.f) atomicAdd(&g_deg2[d], ea);
}

// proj = out2 @ W_f1  ([N,128]x[128,64]); b_c2 cancels in the pairwise diff so skipped
__global__ void k_proj(const float* __restrict__ Wf1) {
    __shared__ float W1s[C2 * HID];
    for (int i = threadIdx.x; i < C2 * HID; i += blockDim.x) W1s[i] = Wf1[i];
    __syncthreads();
    int t = blockIdx.x * blockDim.x + threadIdx.x;
    int node = t >> 6;
    int j = t & 63;
    if (node >= NN) return;
    const float* row = g_out2 + (size_t)node * C2;
    float acc = 0.f;
#pragma unroll 8
    for (int k = 0; k < C2; k++) acc = fmaf(row[k], W1s[k * HID + j], acc);
    g_proj[(size_t)node * HID + j] = acc;
}

// final: sigmoid( relu(proj[a]-proj[b]+b_f1) @ W_f2 + b_f2 )
// half-warp (16 lanes) per edge, float4 loads
__global__ void k_final(const int* __restrict__ ea, const int* __restrict__ eb,
                        const float* __restrict__ bf1, const float* __restrict__ Wf2,
                        const float* __restrict__ bf2, float* __restrict__ out) {
    int t = blockIdx.x * blockDim.x + threadIdx.x;
    int e = t >> 4;
    if (e >= NE) return;
    int l16 = t & 15;
    int a = ea[e], b = eb[e];
    float4 va = ((const float4*)(g_proj + (size_t)a * HID))[l16];
    float4 vb = ((const float4*)(g_proj + (size_t)b * HID))[l16];
    float4 bb = ((const float4*)bf1)[l16];
    float4 w  = ((const float4*)Wf2)[l16];
    float acc = fmaxf(va.x - vb.x + bb.x, 0.f) * w.x
              + fmaxf(va.y - vb.y + bb.y, 0.f) * w.y
              + fmaxf(va.z - vb.z + bb.z, 0.f) * w.z
              + fmaxf(va.w - vb.w + bb.w, 0.f) * w.w;
#pragma unroll
    for (int off = 8; off > 0; off >>= 1)
        acc += __shfl_down_sync(0xFFFFFFFFu, acc, off, 16);
    if (l16 == 0) {
        float z = acc + bf2[0];
        out[e] = 1.f / (1.f + expf(-z));
    }
}

// ---------------- launcher ---------------------------------------------------
extern "C" void kernel_launch(void* const* d_in, const int* in_sizes, int n_in,
                              void* d_out, int out_size) {
    const float* x      = (const float*)d_in[0];
    const float* coords = (const float*)d_in[1];
    const float* W_app  = (const float*)d_in[2];
    const float* b_app  = (const float*)d_in[3];
    const float* W_geom = (const float*)d_in[4];
    const float* b_geom = (const float*)d_in[5];
    const float* W_aff  = (const float*)d_in[6];
    const float* b_aff  = (const float*)d_in[7];
    const float* W_c1   = (const float*)d_in[8];
    const float* b_c1   = (const float*)d_in[9];
    const float* W_m1   = (const float*)d_in[10];
    const float* b_m1   = (const float*)d_in[11];
    const float* W_c2   = (const float*)d_in[12];
    // d_in[13] = b_c2 (cancels in pairwise diff; unused)
    const float* W_f1   = (const float*)d_in[14];
    const float* b_f1   = (const float*)d_in[15];
    const float* W_f2   = (const float*)d_in[16];
    const float* b_f2   = (const float*)d_in[17];
    const int* ei  = (const int*)d_in[18];
    const int* ei2 = (const int*)d_in[19];
    const int* src = ei;
    const int* dst = ei + NE;

    float *h1p, *out1p, *h2p;
    cudaGetSymbolAddress((void**)&h1p, g_h1);
    cudaGetSymbolAddress((void**)&out1p, g_out1);
    cudaGetSymbolAddress((void**)&h2p, g_h2);

    // 0
    k_node_dots<<<(NN + 7) / 8, 256>>>(x, coords, W_app, W_geom);
    // 1
    k_edge1<<<(NE + 255) / 256, 256>>>(src, dst, W_aff, b_app, b_geom, b_aff);
    // 2
    k_scan<<<1, 1024>>>();
    // 3
    k_place<<<(NE + 255) / 256, 256>>>(src, dst);
    // 4
    k_dinv1<<<(NN + 255) / 256, 256>>>();
    // 5: GEMM1 (h1 = x @ W_c1)
    k_gemm_tf32<0><<<dim3((NN + 127) / 128, C1 / 128), 256>>>(
        x, W_c1, h1p, NN, C1, DIN, nullptr);
    // 6: GCN1 aggregation (gather)
    k_gather1<<<(NN * 32 + 255) / 256, 256>>>();
    // 7
    k_mdots<<<(NN + 7) / 8, 256>>>(W_m1, b_c1);
    // 8
    k_edge2<<<(NE + 255) / 256, 256>>>(src, dst, b_m1);
    // 9
    k_dinv2<<<(NN + 255) / 256, 256>>>();
    // 10: GEMM2 (A = relu(out1 + b_c1) inline)
    k_gemm_tf32<1><<<dim3((NN + 127) / 128, C2 / 128), 256>>>(
        out1p, W_c2, h2p, NN, C2, C1, b_c1);
    // 11: GCN2 aggregation (gather)
    k_gather2<<<(NN * 32 + 255) / 256, 256>>>();
    // 12
    k_proj<<<(NN * HID + 511) / 512, 512>>>(W_f1);
    // 13
    k_final<<<(NE * 16 + 255) / 256, 256>>>(ei2, ei2 + NE, b_f1, W_f2, b_f2,
                                            (float*)d_out);
}

// round 14
// speedup vs baseline: 1.1151x; 1.0570x over previous
#include <cuda_runtime.h>
#include <cuda_bf16.h>
#include <math.h>
#include <stdint.h>
#include <stddef.h>

// Problem constants (fixed by the dataset)
#define NN 50000
#define NE 800000
#define DIN 512
#define C1 256
#define C2 128
#define HID 64

// ---------------- scratch (device globals; no allocations allowed) ----------
__device__ float g_app_s[NN];
__device__ float g_app_d[NN];
__device__ float g_geo_s[NN];
__device__ float g_geo_d[NN];
__device__ float g_ew1[NE];
__device__ float g_deg1[NN];   // deg, then overwritten with dinv
__device__ float g_ms[NN];
__device__ float g_md[NN];
__device__ float g_ew2[NE];
__device__ float g_deg2[NN];
__device__ float g_h1[(size_t)NN * C1];
__device__ float g_out1[(size_t)NN * C1];   // pre-bias GCN1 result
__device__ float g_h2[(size_t)NN * C2];
__device__ float g_out2[(size_t)NN * C2];
__device__ float g_proj[(size_t)NN * HID];
// dst-CSR (rebuilt every launch; shared by both GCN layers)
__device__ int  g_cnt[NN];      // per-dst edge count (all edges)
__device__ int  g_rowptr[NN];   // exclusive prefix of g_cnt
__device__ int  g_woff[NN];     // write cursors for placement
__device__ int2 g_csr[NE];      // {src, edge_id} per slot

// ---------------- helpers ----------------------------------------------------
__device__ __forceinline__ float warpReduceSum(float v) {
#pragma unroll
    for (int off = 16; off > 0; off >>= 1)
        v += __shfl_down_sync(0xFFFFFFFFu, v, off);
    return v;
}

// Raw f32 bits as tf32 operand (truncation; error budget has >5x margin).
__device__ __forceinline__ uint32_t f2tf(float f) {
    return __float_as_uint(f);
}

__device__ __forceinline__ void mma_tf32(float* c, const uint32_t* a, const uint32_t* b) {
    asm volatile(
        "mma.sync.aligned.m16n8k8.row.col.f32.tf32.tf32.f32 "
        "{%0,%1,%2,%3}, {%4,%5,%6,%7}, {%8,%9}, {%0,%1,%2,%3};"
        : "+f"(c[0]), "+f"(c[1]), "+f"(c[2]), "+f"(c[3])
        : "r"(a[0]), "r"(a[1]), "r"(a[2]), "r"(a[3]), "r"(b[0]), "r"(b[1]));
}

#define CP_ASYNC16(dst, src) \
    asm volatile("cp.async.cg.shared.global [%0], [%1], 16;" :: "r"(dst), "l"(src))
#define CP_COMMIT asm volatile("cp.async.commit_group;")
template <int N>
__device__ __forceinline__ void cp_wait() {
    asm volatile("cp.async.wait_group %0;" :: "n"(N));
}

// ---------------- kernels ----------------------------------------------------

// node dots + zero degree and CSR-count accumulators (fused)
__global__ void k_node_dots(const float* __restrict__ x,
                            const float* __restrict__ coords,
                            const float* __restrict__ Wapp,
                            const float* __restrict__ Wgeom) {
    int gw = (blockIdx.x * blockDim.x + threadIdx.x) >> 5;
    int lane = threadIdx.x & 31;
    if (gw >= NN) return;
    const float4* row = (const float4*)(x + (size_t)gw * DIN);
    const float4* wa = (const float4*)Wapp;
    float s = 0.f, d = 0.f;
#pragma unroll
    for (int i = 0; i < 4; i++) {
        int idx = lane + 32 * i;
        float4 v = row[idx];
        float4 ws = wa[idx];
        float4 wd = wa[idx + 128];
        s += v.x * ws.x + v.y * ws.y + v.z * ws.z + v.w * ws.w;
        d += v.x * wd.x + v.y * wd.y + v.z * wd.z + v.w * wd.w;
    }
    s = warpReduceSum(s);
    d = warpReduceSum(d);
    if (lane == 0) {
        g_app_s[gw] = s;
        g_app_d[gw] = d;
        float4 c = ((const float4*)coords)[gw];
        g_geo_s[gw] = c.x * Wgeom[0] + c.y * Wgeom[1] + c.z * Wgeom[2] + c.w * Wgeom[3];
        g_geo_d[gw] = c.x * Wgeom[4] + c.y * Wgeom[5] + c.z * Wgeom[6] + c.w * Wgeom[7];
        g_deg1[gw] = 0.f;
        g_deg2[gw] = 0.f;
        g_cnt[gw] = 0;
    }
}

// edge weights for GCN1 + degree + CSR histogram
__global__ void k_edge1(const int* __restrict__ src, const int* __restrict__ dst,
                        const float* __restrict__ Waff,
                        const float* __restrict__ bapp,
                        const float* __restrict__ bgeom,
                        const float* __restrict__ baff) {
    int e = blockIdx.x * blockDim.x + threadIdx.x;
    if (e >= NE) return;
    int s = src[e], d = dst[e];
    float x1 = fmaxf(g_app_s[s] + g_app_d[d] + bapp[0], 0.f);
    float x2 = fmaxf(g_geo_s[s] + g_geo_d[d] + bgeom[0], 0.f);
    float ew = fmaxf(x1 * Waff[0] + x2 * Waff[1] + baff[0], 0.f);
    g_ew1[e] = ew;
    if (ew != 0.f) atomicAdd(&g_deg1[d], ew);
    atomicAdd(&g_cnt[d], 1);
}

// exclusive prefix sum over g_cnt (single block, 1024 threads)
__global__ void k_scan() {
    __shared__ int part[1024];
    const int t = threadIdx.x;
    const int per = (NN + 1023) / 1024;   // 49
    const int base = t * per;
    int sum = 0;
    for (int i = 0; i < per; i++) {
        int idx = base + i;
        if (idx < NN) sum += g_cnt[idx];
    }
    part[t] = sum;
    __syncthreads();
    for (int off = 1; off < 1024; off <<= 1) {
        int v = (t >= off) ? part[t - off] : 0;
        __syncthreads();
        part[t] += v;
        __syncthreads();
    }
    int run = (t > 0) ? part[t - 1] : 0;
    for (int i = 0; i < per; i++) {
        int idx = base + i;
        if (idx < NN) {
            g_rowptr[idx] = run;
            g_woff[idx] = run;
            run += g_cnt[idx];
        }
    }
}

// place edges into CSR slots
__global__ void k_place(const int* __restrict__ src, const int* __restrict__ dst) {
    int e = blockIdx.x * blockDim.x + threadIdx.x;
    if (e >= NE) return;
    int d = dst[e];
    int pos = atomicAdd(&g_woff[d], 1);
    g_csr[pos] = make_int2(src[e], e);
}

__global__ void k_dinv1() {
    int i = blockIdx.x * blockDim.x + threadIdx.x;
    if (i < NN) g_deg1[i] = rsqrtf(g_deg1[i] + 1.0f);  // +1 self-loop; deg>=1
}

__global__ void k_dinv2() {
    int i = blockIdx.x * blockDim.x + threadIdx.x;
    if (i < NN) g_deg2[i] = rsqrtf(g_deg2[i] + 1.0f);
}

// ---------------- TF32 tensor-core GEMM --------------------------------------
// C[M,N] = A[M,K] @ B[K,N], row-major. Block tile 128x128x16, 8 warps,
// warp tile 32x64 via m16n8k8. cp.async double buffer.
// MODE bit0: apply relu(a + biasA[k]) to A fragments.
#define GA_BM 128
#define GA_BK 16
#define GA_AS_STRIDE 20
#define GA_BS_STRIDE 136

template <int MODE>
__global__ __launch_bounds__(256) void k_gemm_tf32(
    const float* __restrict__ A, const float* __restrict__ B,
    float* __restrict__ C, int M, int N, int K,
    const float* __restrict__ biasA) {
    __shared__ __align__(16) float As[2][GA_BM * GA_AS_STRIDE];
    __shared__ __align__(16) float Bs[2][GA_BK * GA_BS_STRIDE];

    const int tid = threadIdx.x;
    const int lane = tid & 31;
    const int wid = tid >> 5;
    const int wm = wid & 3;
    const int wn = wid >> 2;
    const int grp = lane >> 2;
    const int qid = lane & 3;

    const int row0 = blockIdx.x * GA_BM;
    const int col0 = blockIdx.y * 128;

    const int ar0 = tid >> 2;
    const int ac = (tid & 3) * 4;
    const int br0 = tid >> 5;
    const int bc = (tid & 31) * 4;

    const int arow_g0 = min(row0 + ar0, M - 1);
    const int arow_g1 = min(row0 + ar0 + 64, M - 1);

    float acc[2][8][4];
#pragma unroll
    for (int mt = 0; mt < 2; mt++)
#pragma unroll
        for (int nt = 0; nt < 8; nt++)
#pragma unroll
            for (int i = 0; i < 4; i++) acc[mt][nt][i] = 0.f;

    auto load_tile = [&](int buf, int k0) {
        uint32_t a_s0 = (uint32_t)__cvta_generic_to_shared(
            &As[buf][ar0 * GA_AS_STRIDE + ac]);
        uint32_t a_s1 = (uint32_t)__cvta_generic_to_shared(
            &As[buf][(ar0 + 64) * GA_AS_STRIDE + ac]);
        CP_ASYNC16(a_s0, A + (size_t)arow_g0 * K + k0 + ac);
        CP_ASYNC16(a_s1, A + (size_t)arow_g1 * K + k0 + ac);
        uint32_t b_s0 = (uint32_t)__cvta_generic_to_shared(
            &Bs[buf][br0 * GA_BS_STRIDE + bc]);
        uint32_t b_s1 = (uint32_t)__cvta_generic_to_shared(
            &Bs[buf][(br0 + 8) * GA_BS_STRIDE + bc]);
        CP_ASYNC16(b_s0, B + (size_t)(k0 + br0) * N + col0 + bc);
        CP_ASYNC16(b_s1, B + (size_t)(k0 + br0 + 8) * N + col0 + bc);
    };

    const int ntiles = K / GA_BK;
    load_tile(0, 0);
    CP_COMMIT;

    int buf = 0;
    const int arow_base = wm * 32 + grp;
    const int bcol_base = wn * 64 + grp;

    for (int t = 0; t < ntiles; t++) {
        const int k0 = t * GA_BK;
        if (t + 1 < ntiles) {
            load_tile(buf ^ 1, (t + 1) * GA_BK);
            CP_COMMIT;
            cp_wait<1>();
        } else {
            cp_wait<0>();
        }
        __syncthreads();

        const float* as = As[buf];
        const float* bs = Bs[buf];
#pragma unroll
        for (int ks = 0; ks < 2; ks++) {
            const int kk = ks * 8 + qid;
            float ab0 = 0.f, ab1 = 0.f;
            if (MODE & 1) {
                ab0 = biasA[k0 + kk];
                ab1 = biasA[k0 + kk + 4];
            }
            uint32_t a[2][4];
#pragma unroll
            for (int mt = 0; mt < 2; mt++) {
                const float* ap = as + (arow_base + mt * 16) * GA_AS_STRIDE + kk;
                float v0 = ap[0];
                float v1 = ap[8 * GA_AS_STRIDE];
                float v2 = ap[4];
                float v3 = ap[8 * GA_AS_STRIDE + 4];
                if (MODE & 1) {
                    v0 = fmaxf(v0 + ab0, 0.f);
                    v1 = fmaxf(v1 + ab0, 0.f);
                    v2 = fmaxf(v2 + ab1, 0.f);
                    v3 = fmaxf(v3 + ab1, 0.f);
                }
                a[mt][0] = f2tf(v0);
                a[mt][1] = f2tf(v1);
                a[mt][2] = f2tf(v2);
                a[mt][3] = f2tf(v3);
            }
            const float* bp = bs + kk * GA_BS_STRIDE + bcol_base;
#pragma unroll
            for (int nt = 0; nt < 8; nt++) {
                uint32_t b[2];
                b[0] = f2tf(bp[nt * 8]);
                b[1] = f2tf(bp[4 * GA_BS_STRIDE + nt * 8]);
                mma_tf32(acc[0][nt], a[0], b);
                mma_tf32(acc[1][nt], a[1], b);
            }
        }
        __syncthreads();
        buf ^= 1;
    }

#pragma unroll
    for (int mt = 0; mt < 2; mt++) {
        int r = row0 + wm * 32 + mt * 16 + grp;
#pragma unroll
        for (int nt = 0; nt < 8; nt++) {
            int c = col0 + wn * 64 + nt * 8 + qid * 2;
            if (r < M)
                *(float2*)(C + (size_t)r * N + c) =
                    make_float2(acc[mt][nt][0], acc[mt][nt][1]);
            if (r + 8 < M)
                *(float2*)(C + (size_t)(r + 8) * N + c) =
                    make_float2(acc[mt][nt][2], acc[mt][nt][3]);
        }
    }
}

// GCN1 aggregation: gather per dst node (warp per node). out1[d] =
// dinv1[d]^2*h1[d] + sum_e coef_e * h1[src_e].  256-dim: 2 float4/lane.
__global__ void k_gather1() {
    int node = (blockIdx.x * blockDim.x + threadIdx.x) >> 5;
    if (node >= NN) return;
    int lane = threadIdx.x & 31;
    int start = g_rowptr[node];
    int cnt = g_cnt[node];
    float di = g_deg1[node];
    const float4* hd = (const float4*)(g_h1 + (size_t)node * C1);
    float self = di * di;
    float4 v0 = hd[lane], v1 = hd[lane + 32];
    float4 acc0 = make_float4(self * v0.x, self * v0.y, self * v0.z, self * v0.w);
    float4 acc1 = make_float4(self * v1.x, self * v1.y, self * v1.z, self * v1.w);
    for (int i = 0; i < cnt; i++) {
        int2 se = g_csr[start + i];
        float ew = g_ew1[se.y];
        if (ew == 0.f) continue;
        float coef = g_deg1[se.x] * ew * di;
        const float4* hs = (const float4*)(g_h1 + (size_t)se.x * C1);
        float4 a = hs[lane], b = hs[lane + 32];
        acc0.x += coef * a.x; acc0.y += coef * a.y;
        acc0.z += coef * a.z; acc0.w += coef * a.w;
        acc1.x += coef * b.x; acc1.y += coef * b.y;
        acc1.z += coef * b.z; acc1.w += coef * b.w;
    }
    float4* od = (float4*)(g_out1 + (size_t)node * C1);
    od[lane] = acc0;
    od[lane + 32] = acc1;
}

// GCN2 aggregation: same, 128-dim: 1 float4/lane.
__global__ void k_gather2() {
    int node = (blockIdx.x * blockDim.x + threadIdx.x) >> 5;
    if (node >= NN) return;
    int lane = threadIdx.x & 31;
    int start = g_rowptr[node];
    int cnt = g_cnt[node];
    float di = g_deg2[node];
    const float4* hd = (const float4*)(g_h2 + (size_t)node * C2);
    float self = di * di;
    float4 v0 = hd[lane];
    float4 acc = make_float4(self * v0.x, self * v0.y, self * v0.z, self * v0.w);
    for (int i = 0; i < cnt; i++) {
        int2 se = g_csr[start + i];
        float ew = g_ew2[se.y];
        if (ew == 0.f) continue;
        float coef = g_deg2[se.x] * ew * di;
        const float4* hs = (const float4*)(g_h2 + (size_t)se.x * C2);
        float4 a = hs[lane];
        acc.x += coef * a.x; acc.y += coef * a.y;
        acc.z += coef * a.z; acc.w += coef * a.w;
    }
    ((float4*)(g_out2 + (size_t)node * C2))[lane] = acc;
}

// m_s / m_d dots over relu(out1 + b_c1), warp per node (bias+relu inline)
__global__ void k_mdots(const float* __restrict__ Wm1, const float* __restrict__ bc1) {
    int gw = (blockIdx.x * blockDim.x + threadIdx.x) >> 5;
    int lane = threadIdx.x & 31;
    if (gw >= NN) return;
    const float4* row = (const float4*)(g_out1 + (size_t)gw * C1);
    const float4* wm = (const float4*)Wm1;
    const float4* bb = (const float4*)bc1;
    float s = 0.f, d = 0.f;
#pragma unroll
    for (int i = 0; i < 2; i++) {
        int idx = lane + 32 * i;
        float4 v = row[idx];
        float4 b = bb[idx];
        v.x = fmaxf(v.x + b.x, 0.f);
        v.y = fmaxf(v.y + b.y, 0.f);
        v.z = fmaxf(v.z + b.z, 0.f);
        v.w = fmaxf(v.w + b.w, 0.f);
        float4 ws = wm[idx];
        float4 wd = wm[idx + 64];
        s += v.x * ws.x + v.y * ws.y + v.z * ws.z + v.w * ws.w;
        d += v.x * wd.x + v.y * wd.y + v.z * wd.z + v.w * wd.w;
    }
    s = warpReduceSum(s);
    d = warpReduceSum(d);
    if (lane == 0) { g_ms[gw] = s; g_md[gw] = d; }
}

__global__ void k_edge2(const int* __restrict__ src, const int* __restrict__ dst,
                        const float* __restrict__ bm1) {
    int e = blockIdx.x * blockDim.x + threadIdx.x;
    if (e >= NE) return;
    int s = src[e], d = dst[e];
    float ea = fmaxf(g_ms[s] + g_md[d] + bm1[0], 0.f);
    g_ew2[e] = ea;
    if (ea != 0.f) atomicAdd(&g_deg2[d], ea);
}

// proj = out2 @ W_f1  ([N,128]x[128,64]); b_c2 cancels in the pairwise diff so skipped
__global__ void k_proj(const float* __restrict__ Wf1) {
    __shared__ float W1s[C2 * HID];
    for (int i = threadIdx.x; i < C2 * HID; i += blockDim.x) W1s[i] = Wf1[i];
    __syncthreads();
    int t = blockIdx.x * blockDim.x + threadIdx.x;
    int node = t >> 6;
    int j = t & 63;
    if (node >= NN) return;
    const float* row = g_out2 + (size_t)node * C2;
    float acc = 0.f;
#pragma unroll 8
    for (int k = 0; k < C2; k++) acc = fmaf(row[k], W1s[k * HID + j], acc);
    g_proj[(size_t)node * HID + j] = acc;
}

// final: sigmoid( relu(proj[a]-proj[b]+b_f1) @ W_f2 + b_f2 )
// half-warp (16 lanes) per edge, float4 loads
__global__ void k_final(const int* __restrict__ ea, const int* __restrict__ eb,
                        const float* __restrict__ bf1, const float* __restrict__ Wf2,
                        const float* __restrict__ bf2, float* __restrict__ out) {
    int t = blockIdx.x * blockDim.x + threadIdx.x;
    int e = t >> 4;
    if (e >= NE) return;
    int l16 = t & 15;
    int a = ea[e], b = eb[e];
    float4 va = ((const float4*)(g_proj + (size_t)a * HID))[l16];
    float4 vb = ((const float4*)(g_proj + (size_t)b * HID))[l16];
    float4 bb = ((const float4*)bf1)[l16];
    float4 w  = ((const float4*)Wf2)[l16];
    float acc = fmaxf(va.x - vb.x + bb.x, 0.f) * w.x
              + fmaxf(va.y - vb.y + bb.y, 0.f) * w.y
              + fmaxf(va.z - vb.z + bb.z, 0.f) * w.z
              + fmaxf(va.w - vb.w + bb.w, 0.f) * w.w;
#pragma unroll
    for (int off = 8; off > 0; off >>= 1)
        acc += __shfl_down_sync(0xFFFFFFFFu, acc, off, 16);
    if (l16 == 0) {
        float z = acc + bf2[0];
        out[e] = 1.f / (1.f + expf(-z));
    }
}

// ---------------- launcher ---------------------------------------------------
extern "C" void kernel_launch(void* const* d_in, const int* in_sizes, int n_in,
                              void* d_out, int out_size) {
    const float* x      = (const float*)d_in[0];
    const float* coords = (const float*)d_in[1];
    const float* W_app  = (const float*)d_in[2];
    const float* b_app  = (const float*)d_in[3];
    const float* W_geom = (const float*)d_in[4];
    const float* b_geom = (const float*)d_in[5];
    const float* W_aff  = (const float*)d_in[6];
    const float* b_aff  = (const float*)d_in[7];
    const float* W_c1   = (const float*)d_in[8];
    const float* b_c1   = (const float*)d_in[9];
    const float* W_m1   = (const float*)d_in[10];
    const float* b_m1   = (const float*)d_in[11];
    const float* W_c2   = (const float*)d_in[12];
    // d_in[13] = b_c2 (cancels in pairwise diff; unused)
    const float* W_f1   = (const float*)d_in[14];
    const float* b_f1   = (const float*)d_in[15];
    const float* W_f2   = (const float*)d_in[16];
    const float* b_f2   = (const float*)d_in[17];
    const int* ei  = (const int*)d_in[18];
    const int* ei2 = (const int*)d_in[19];
    const int* src = ei;
    const int* dst = ei + NE;

    float *h1p, *out1p, *h2p;
    cudaGetSymbolAddress((void**)&h1p, g_h1);
    cudaGetSymbolAddress((void**)&out1p, g_out1);
    cudaGetSymbolAddress((void**)&h2p, g_h2);

    // Second stream + events (created once, outside capture; the harness's
    // first call is the uncaptured correctness run). Cross-stream event
    // dependencies are capturable and become graph edges.
    static cudaStream_t sB = nullptr;
    static cudaEvent_t evFork = nullptr, evG1 = nullptr, evGa1 = nullptr, evG2 = nullptr;
    if (sB == nullptr) {
        cudaStreamCreateWithFlags(&sB, cudaStreamNonBlocking);
        cudaEventCreateWithFlags(&evFork, cudaEventDisableTiming);
        cudaEventCreateWithFlags(&evG1, cudaEventDisableTiming);
        cudaEventCreateWithFlags(&evGa1, cudaEventDisableTiming);
        cudaEventCreateWithFlags(&evG2, cudaEventDisableTiming);
    }
    cudaStream_t sA = 0;  // default (capture) stream

    // fork: sB joins the capture
    cudaEventRecord(evFork, sA);
    cudaStreamWaitEvent(sB, evFork, 0);

    // --- island 1: GEMM1 (sB) || edge/CSR prep (sA) ---
    k_gemm_tf32<0><<<dim3((NN + 127) / 128, C1 / 128), 256, 0, sB>>>(
        x, W_c1, h1p, NN, C1, DIN, nullptr);
    cudaEventRecord(evG1, sB);

    k_node_dots<<<(NN + 7) / 8, 256, 0, sA>>>(x, coords, W_app, W_geom);
    k_edge1<<<(NE + 255) / 256, 256, 0, sA>>>(src, dst, W_aff, b_app, b_geom, b_aff);
    k_scan<<<1, 1024, 0, sA>>>();
    k_place<<<(NE + 255) / 256, 256, 0, sA>>>(src, dst);
    k_dinv1<<<(NN + 255) / 256, 256, 0, sA>>>();

    // join: gather1 needs h1 (sB) + CSR/dinv1 (sA)
    cudaStreamWaitEvent(sA, evG1, 0);
    k_gather1<<<(NN * 32 + 255) / 256, 256, 0, sA>>>();
    cudaEventRecord(evGa1, sA);

    // --- island 2: GEMM2 (sB) || mdots->edge2->dinv2 (sA) ---
    cudaStreamWaitEvent(sB, evGa1, 0);
    k_gemm_tf32<1><<<dim3((NN + 127) / 128, C2 / 128), 256, 0, sB>>>(
        out1p, W_c2, h2p, NN, C2, C1, b_c1);
    cudaEventRecord(evG2, sB);

    k_mdots<<<(NN + 7) / 8, 256, 0, sA>>>(W_m1, b_c1);
    k_edge2<<<(NE + 255) / 256, 256, 0, sA>>>(src, dst, b_m1);
    k_dinv2<<<(NN + 255) / 256, 256, 0, sA>>>();

    // join: gather2 needs h2 (sB) + ew2/dinv2 (sA)
    cudaStreamWaitEvent(sA, evG2, 0);
    k_gather2<<<(NN * 32 + 255) / 256, 256, 0, sA>>>();
    k_proj<<<(NN * HID + 511) / 512, 512, 0, sA>>>(W_f1);
    k_final<<<(NE * 16 + 255) / 256, 256, 0, sA>>>(ei2, ei2 + NE, b_f1, W_f2, b_f2,
                                                   (float*)d_out);
}

// round 15
// speedup vs baseline: 1.3206x; 1.1842x over previous
#include <cuda_runtime.h>
#include <cuda_bf16.h>
#include <math.h>
#include <stdint.h>
#include <stddef.h>

// Problem constants (fixed by the dataset)
#define NN 50000
#define NE 800000
#define DIN 512
#define C1 256
#define C2 128
#define HID 64
#define NB ((NN + 255) / 256)   // 196 scan blocks

// ---------------- scratch (device globals; no allocations allowed) ----------
__device__ float g_app_s[NN];
__device__ float g_app_d[NN];
__device__ float g_geo_s[NN];
__device__ float g_geo_d[NN];
__device__ float g_ew1[NE];
__device__ float g_deg1[NN];   // deg, then overwritten with dinv
__device__ float g_ms[NN];
__device__ float g_md[NN];
__device__ float g_ew2[NE];
__device__ float g_deg2[NN];
__device__ float g_h1[(size_t)NN * C1];
__device__ float g_out1[(size_t)NN * C1];   // pre-bias GCN1 result
__device__ float g_h2[(size_t)NN * C2];
__device__ float g_proj[(size_t)NN * HID];
// dst-CSR (rebuilt every launch; shared by both GCN layers)
__device__ int  g_cnt[NN];      // per-dst edge count (all edges)
__device__ int  g_rowptr[NN];   // exclusive prefix of g_cnt
__device__ int  g_woff[NN];     // write cursors for placement
__device__ int  g_bsum[256];    // scan block partials
__device__ int2 g_csr[NE];      // {src, edge_id} per slot

// ---------------- helpers ----------------------------------------------------
__device__ __forceinline__ float warpReduceSum(float v) {
#pragma unroll
    for (int off = 16; off > 0; off >>= 1)
        v += __shfl_down_sync(0xFFFFFFFFu, v, off);
    return v;
}

// Raw f32 bits as tf32 operand (truncation; error budget has >5x margin).
__device__ __forceinline__ uint32_t f2tf(float f) {
    return __float_as_uint(f);
}

__device__ __forceinline__ void mma_tf32(float* c, const uint32_t* a, const uint32_t* b) {
    asm volatile(
        "mma.sync.aligned.m16n8k8.row.col.f32.tf32.tf32.f32 "
        "{%0,%1,%2,%3}, {%4,%5,%6,%7}, {%8,%9}, {%0,%1,%2,%3};"
        : "+f"(c[0]), "+f"(c[1]), "+f"(c[2]), "+f"(c[3])
        : "r"(a[0]), "r"(a[1]), "r"(a[2]), "r"(a[3]), "r"(b[0]), "r"(b[1]));
}

#define CP_ASYNC16(dst, src) \
    asm volatile("cp.async.cg.shared.global [%0], [%1], 16;" :: "r"(dst), "l"(src))
#define CP_COMMIT asm volatile("cp.async.commit_group;")
template <int N>
__device__ __forceinline__ void cp_wait() {
    asm volatile("cp.async.wait_group %0;" :: "n"(N));
}

// ---------------- kernels ----------------------------------------------------

// node dots + zero degree and CSR-count accumulators (fused)
__global__ void k_node_dots(const float* __restrict__ x,
                            const float* __restrict__ coords,
                            const float* __restrict__ Wapp,
                            const float* __restrict__ Wgeom) {
    int gw = (blockIdx.x * blockDim.x + threadIdx.x) >> 5;
    int lane = threadIdx.x & 31;
    if (gw >= NN) return;
    const float4* row = (const float4*)(x + (size_t)gw * DIN);
    const float4* wa = (const float4*)Wapp;
    float s = 0.f, d = 0.f;
#pragma unroll
    for (int i = 0; i < 4; i++) {
        int idx = lane + 32 * i;
        float4 v = row[idx];
        float4 ws = wa[idx];
        float4 wd = wa[idx + 128];
        s += v.x * ws.x + v.y * ws.y + v.z * ws.z + v.w * ws.w;
        d += v.x * wd.x + v.y * wd.y + v.z * wd.z + v.w * wd.w;
    }
    s = warpReduceSum(s);
    d = warpReduceSum(d);
    if (lane == 0) {
        g_app_s[gw] = s;
        g_app_d[gw] = d;
        float4 c = ((const float4*)coords)[gw];
        g_geo_s[gw] = c.x * Wgeom[0] + c.y * Wgeom[1] + c.z * Wgeom[2] + c.w * Wgeom[3];
        g_geo_d[gw] = c.x * Wgeom[4] + c.y * Wgeom[5] + c.z * Wgeom[6] + c.w * Wgeom[7];
        g_deg1[gw] = 0.f;
        g_deg2[gw] = 0.f;
        g_cnt[gw] = 0;
    }
}

// edge weights for GCN1 + degree + CSR histogram
__global__ void k_edge1(const int* __restrict__ src, const int* __restrict__ dst,
                        const float* __restrict__ Waff,
                        const float* __restrict__ bapp,
                        const float* __restrict__ bgeom,
                        const float* __restrict__ baff) {
    int e = blockIdx.x * blockDim.x + threadIdx.x;
    if (e >= NE) return;
    int s = src[e], d = dst[e];
    float x1 = fmaxf(g_app_s[s] + g_app_d[d] + bapp[0], 0.f);
    float x2 = fmaxf(g_geo_s[s] + g_geo_d[d] + bgeom[0], 0.f);
    float ew = fmaxf(x1 * Waff[0] + x2 * Waff[1] + baff[0], 0.f);
    g_ew1[e] = ew;
    if (ew != 0.f) atomicAdd(&g_deg1[d], ew);
    atomicAdd(&g_cnt[d], 1);
}

// ---- 3-phase multi-block exclusive scan of g_cnt ----
__global__ void k_scanA() {
    __shared__ int sh[256];
    int idx = blockIdx.x * 256 + threadIdx.x;
    sh[threadIdx.x] = (idx < NN) ? g_cnt[idx] : 0;
    __syncthreads();
#pragma unroll
    for (int off = 128; off > 0; off >>= 1) {
        if (threadIdx.x < off) sh[threadIdx.x] += sh[threadIdx.x + off];
        __syncthreads();
    }
    if (threadIdx.x == 0) g_bsum[blockIdx.x] = sh[0];
}

__global__ void k_scanB() {
    __shared__ int sh[256];
    int t = threadIdx.x;
    sh[t] = (t < NB) ? g_bsum[t] : 0;
    __syncthreads();
    for (int off = 1; off < 256; off <<= 1) {
        int v = (t >= off) ? sh[t - off] : 0;
        __syncthreads();
        sh[t] += v;
        __syncthreads();
    }
    if (t < NB) g_bsum[t] = (t > 0) ? sh[t - 1] : 0;   // exclusive
}

__global__ void k_scanC() {
    __shared__ int sh[256];
    int t = threadIdx.x;
    int idx = blockIdx.x * 256 + t;
    int v = (idx < NN) ? g_cnt[idx] : 0;
    sh[t] = v;
    __syncthreads();
    for (int off = 1; off < 256; off <<= 1) {
        int u = (t >= off) ? sh[t - off] : 0;
        __syncthreads();
        sh[t] += u;
        __syncthreads();
    }
    if (idx < NN) {
        int ex = sh[t] - v + g_bsum[blockIdx.x];
        g_rowptr[idx] = ex;
        g_woff[idx] = ex;
    }
}

// place edges into CSR slots
__global__ void k_place(const int* __restrict__ src, const int* __restrict__ dst) {
    int e = blockIdx.x * blockDim.x + threadIdx.x;
    if (e >= NE) return;
    int d = dst[e];
    int pos = atomicAdd(&g_woff[d], 1);
    g_csr[pos] = make_int2(src[e], e);
}

__global__ void k_dinv1() {
    int i = blockIdx.x * blockDim.x + threadIdx.x;
    if (i < NN) g_deg1[i] = rsqrtf(g_deg1[i] + 1.0f);  // +1 self-loop; deg>=1
}

__global__ void k_dinv2() {
    int i = blockIdx.x * blockDim.x + threadIdx.x;
    if (i < NN) g_deg2[i] = rsqrtf(g_deg2[i] + 1.0f);
}

// ---------------- TF32 tensor-core GEMM --------------------------------------
#define GA_BM 128
#define GA_BK 16
#define GA_AS_STRIDE 20
#define GA_BS_STRIDE 136

template <int MODE>
__global__ __launch_bounds__(256) void k_gemm_tf32(
    const float* __restrict__ A, const float* __restrict__ B,
    float* __restrict__ C, int M, int N, int K,
    const float* __restrict__ biasA) {
    __shared__ __align__(16) float As[2][GA_BM * GA_AS_STRIDE];
    __shared__ __align__(16) float Bs[2][GA_BK * GA_BS_STRIDE];

    const int tid = threadIdx.x;
    const int lane = tid & 31;
    const int wid = tid >> 5;
    const int wm = wid & 3;
    const int wn = wid >> 2;
    const int grp = lane >> 2;
    const int qid = lane & 3;

    const int row0 = blockIdx.x * GA_BM;
    const int col0 = blockIdx.y * 128;

    const int ar0 = tid >> 2;
    const int ac = (tid & 3) * 4;
    const int br0 = tid >> 5;
    const int bc = (tid & 31) * 4;

    const int arow_g0 = min(row0 + ar0, M - 1);
    const int arow_g1 = min(row0 + ar0 + 64, M - 1);

    float acc[2][8][4];
#pragma unroll
    for (int mt = 0; mt < 2; mt++)
#pragma unroll
        for (int nt = 0; nt < 8; nt++)
#pragma unroll
            for (int i = 0; i < 4; i++) acc[mt][nt][i] = 0.f;

    auto load_tile = [&](int buf, int k0) {
        uint32_t a_s0 = (uint32_t)__cvta_generic_to_shared(
            &As[buf][ar0 * GA_AS_STRIDE + ac]);
        uint32_t a_s1 = (uint32_t)__cvta_generic_to_shared(
            &As[buf][(ar0 + 64) * GA_AS_STRIDE + ac]);
        CP_ASYNC16(a_s0, A + (size_t)arow_g0 * K + k0 + ac);
        CP_ASYNC16(a_s1, A + (size_t)arow_g1 * K + k0 + ac);
        uint32_t b_s0 = (uint32_t)__cvta_generic_to_shared(
            &Bs[buf][br0 * GA_BS_STRIDE + bc]);
        uint32_t b_s1 = (uint32_t)__cvta_generic_to_shared(
            &Bs[buf][(br0 + 8) * GA_BS_STRIDE + bc]);
        CP_ASYNC16(b_s0, B + (size_t)(k0 + br0) * N + col0 + bc);
        CP_ASYNC16(b_s1, B + (size_t)(k0 + br0 + 8) * N + col0 + bc);
    };

    const int ntiles = K / GA_BK;
    load_tile(0, 0);
    CP_COMMIT;

    int buf = 0;
    const int arow_base = wm * 32 + grp;
    const int bcol_base = wn * 64 + grp;

    for (int t = 0; t < ntiles; t++) {
        const int k0 = t * GA_BK;
        if (t + 1 < ntiles) {
            load_tile(buf ^ 1, (t + 1) * GA_BK);
            CP_COMMIT;
            cp_wait<1>();
        } else {
            cp_wait<0>();
        }
        __syncthreads();

        const float* as = As[buf];
        const float* bs = Bs[buf];
#pragma unroll
        for (int ks = 0; ks < 2; ks++) {
            const int kk = ks * 8 + qid;
            float ab0 = 0.f, ab1 = 0.f;
            if (MODE & 1) {
                ab0 = biasA[k0 + kk];
                ab1 = biasA[k0 + kk + 4];
            }
            uint32_t a[2][4];
#pragma unroll
            for (int mt = 0; mt < 2; mt++) {
                const float* ap = as + (arow_base + mt * 16) * GA_AS_STRIDE + kk;
                float v0 = ap[0];
                float v1 = ap[8 * GA_AS_STRIDE];
                float v2 = ap[4];
                float v3 = ap[8 * GA_AS_STRIDE + 4];
                if (MODE & 1) {
                    v0 = fmaxf(v0 + ab0, 0.f);
                    v1 = fmaxf(v1 + ab0, 0.f);
                    v2 = fmaxf(v2 + ab1, 0.f);
                    v3 = fmaxf(v3 + ab1, 0.f);
                }
                a[mt][0] = f2tf(v0);
                a[mt][1] = f2tf(v1);
                a[mt][2] = f2tf(v2);
                a[mt][3] = f2tf(v3);
            }
            const float* bp = bs + kk * GA_BS_STRIDE + bcol_base;
#pragma unroll
            for (int nt = 0; nt < 8; nt++) {
                uint32_t b[2];
                b[0] = f2tf(bp[nt * 8]);
                b[1] = f2tf(bp[4 * GA_BS_STRIDE + nt * 8]);
                mma_tf32(acc[0][nt], a[0], b);
                mma_tf32(acc[1][nt], a[1], b);
            }
        }
        __syncthreads();
        buf ^= 1;
    }

#pragma unroll
    for (int mt = 0; mt < 2; mt++) {
        int r = row0 + wm * 32 + mt * 16 + grp;
#pragma unroll
        for (int nt = 0; nt < 8; nt++) {
            int c = col0 + wn * 64 + nt * 8 + qid * 2;
            if (r < M)
                *(float2*)(C + (size_t)r * N + c) =
                    make_float2(acc[mt][nt][0], acc[mt][nt][1]);
            if (r + 8 < M)
                *(float2*)(C + (size_t)(r + 8) * N + c) =
                    make_float2(acc[mt][nt][2], acc[mt][nt][3]);
        }
    }
}

// GCN1 aggregation: gather per dst node (warp per node). out1[d] =
// dinv1[d]^2*h1[d] + sum_e coef_e * h1[src_e].  256-dim: 2 float4/lane.
__global__ void k_gather1() {
    int node = (blockIdx.x * blockDim.x + threadIdx.x) >> 5;
    if (node >= NN) return;
    int lane = threadIdx.x & 31;
    int start = g_rowptr[node];
    int cnt = g_cnt[node];
    float di = g_deg1[node];
    const float4* hd = (const float4*)(g_h1 + (size_t)node * C1);
    float self = di * di;
    float4 v0 = hd[lane], v1 = hd[lane + 32];
    float4 acc0 = make_float4(self * v0.x, self * v0.y, self * v0.z, self * v0.w);
    float4 acc1 = make_float4(self * v1.x, self * v1.y, self * v1.z, self * v1.w);
    for (int i = 0; i < cnt; i++) {
        int2 se = g_csr[start + i];
        float ew = g_ew1[se.y];
        if (ew == 0.f) continue;
        float coef = g_deg1[se.x] * ew * di;
        const float4* hs = (const float4*)(g_h1 + (size_t)se.x * C1);
        float4 a = hs[lane], b = hs[lane + 32];
        acc0.x += coef * a.x; acc0.y += coef * a.y;
        acc0.z += coef * a.z; acc0.w += coef * a.w;
        acc1.x += coef * b.x; acc1.y += coef * b.y;
        acc1.z += coef * b.z; acc1.w += coef * b.w;
    }
    float4* od = (float4*)(g_out1 + (size_t)node * C1);
    od[lane] = acc0;
    od[lane + 32] = acc1;
}

// GCN2 aggregation fused with proj: out2 row stays in smem, proj = row @ W_f1.
// Warp loops over nodes; W_f1 cached in smem once per block.
__global__ __launch_bounds__(256) void k_gather2proj(const float* __restrict__ Wf1) {
    __shared__ float W1s[C2 * HID];     // 32 KB
    __shared__ float rows[8][C2];       // 4 KB, one row per warp
    for (int i = threadIdx.x; i < C2 * HID; i += blockDim.x) W1s[i] = Wf1[i];
    __syncthreads();
    const int lane = threadIdx.x & 31;
    const int wrp = threadIdx.x >> 5;
    const int gw0 = (blockIdx.x * blockDim.x + threadIdx.x) >> 5;
    const int nwarps = (gridDim.x * blockDim.x) >> 5;
    float* row = rows[wrp];
    for (int node = gw0; node < NN; node += nwarps) {
        int start = g_rowptr[node];
        int cnt = g_cnt[node];
        float di = g_deg2[node];
        const float4* hd = (const float4*)(g_h2 + (size_t)node * C2);
        float self = di * di;
        float4 v0 = hd[lane];
        float4 acc = make_float4(self * v0.x, self * v0.y, self * v0.z, self * v0.w);
        for (int i = 0; i < cnt; i++) {
            int2 se = g_csr[start + i];
            float ew = g_ew2[se.y];
            if (ew == 0.f) continue;
            float coef = g_deg2[se.x] * ew * di;
            const float4* hs = (const float4*)(g_h2 + (size_t)se.x * C2);
            float4 a = hs[lane];
            acc.x += coef * a.x; acc.y += coef * a.y;
            acc.z += coef * a.z; acc.w += coef * a.w;
        }
        ((float4*)row)[lane] = acc;
        __syncwarp();
        float p0 = 0.f, p1 = 0.f;
#pragma unroll 8
        for (int k = 0; k < C2; k++) {
            float rv = row[k];
            p0 = fmaf(rv, W1s[k * HID + lane], p0);
            p1 = fmaf(rv, W1s[k * HID + lane + 32], p1);
        }
        g_proj[(size_t)node * HID + lane] = p0;
        g_proj[(size_t)node * HID + lane + 32] = p1;
        __syncwarp();
    }
}

// m_s / m_d dots over relu(out1 + b_c1), warp per node (bias+relu inline)
__global__ void k_mdots(const float* __restrict__ Wm1, const float* __restrict__ bc1) {
    int gw = (blockIdx.x * blockDim.x + threadIdx.x) >> 5;
    int lane = threadIdx.x & 31;
    if (gw >= NN) return;
    const float4* row = (const float4*)(g_out1 + (size_t)gw * C1);
    const float4* wm = (const float4*)Wm1;
    const float4* bb = (const float4*)bc1;
    float s = 0.f, d = 0.f;
#pragma unroll
    for (int i = 0; i < 2; i++) {
        int idx = lane + 32 * i;
        float4 v = row[idx];
        float4 b = bb[idx];
        v.x = fmaxf(v.x + b.x, 0.f);
        v.y = fmaxf(v.y + b.y, 0.f);
        v.z = fmaxf(v.z + b.z, 0.f);
        v.w = fmaxf(v.w + b.w, 0.f);
        float4 ws = wm[idx];
        float4 wd = wm[idx + 64];
        s += v.x * ws.x + v.y * ws.y + v.z * ws.z + v.w * ws.w;
        d += v.x * wd.x + v.y * wd.y + v.z * wd.z + v.w * wd.w;
    }
    s = warpReduceSum(s);
    d = warpReduceSum(d);
    if (lane == 0) { g_ms[gw] = s; g_md[gw] = d; }
}

__global__ void k_edge2(const int* __restrict__ src, const int* __restrict__ dst,
                        const float* __restrict__ bm1) {
    int e = blockIdx.x * blockDim.x + threadIdx.x;
    if (e >= NE) return;
    int s = src[e], d = dst[e];
    float ea = fmaxf(g_ms[s] + g_md[d] + bm1[0], 0.f);
    g_ew2[e] = ea;
    if (ea != 0.f) atomicAdd(&g_deg2[d], ea);
}

// final: sigmoid( relu(proj[a]-proj[b]+b_f1) @ W_f2 + b_f2 )
// half-warp (16 lanes) per edge, float4 loads
__global__ void k_final(const int* __restrict__ ea, const int* __restrict__ eb,
                        const float* __restrict__ bf1, const float* __restrict__ Wf2,
                        const float* __restrict__ bf2, float* __restrict__ out) {
    int t = blockIdx.x * blockDim.x + threadIdx.x;
    int e = t >> 4;
    if (e >= NE) return;
    int l16 = t & 15;
    int a = ea[e], b = eb[e];
    float4 va = ((const float4*)(g_proj + (size_t)a * HID))[l16];
    float4 vb = ((const float4*)(g_proj + (size_t)b * HID))[l16];
    float4 bb = ((const float4*)bf1)[l16];
    float4 w  = ((const float4*)Wf2)[l16];
    float acc = fmaxf(va.x - vb.x + bb.x, 0.f) * w.x
              + fmaxf(va.y - vb.y + bb.y, 0.f) * w.y
              + fmaxf(va.z - vb.z + bb.z, 0.f) * w.z
              + fmaxf(va.w - vb.w + bb.w, 0.f) * w.w;
#pragma unroll
    for (int off = 8; off > 0; off >>= 1)
        acc += __shfl_down_sync(0xFFFFFFFFu, acc, off, 16);
    if (l16 == 0) {
        float z = acc + bf2[0];
        out[e] = 1.f / (1.f + expf(-z));
    }
}

// ---------------- launcher ---------------------------------------------------
extern "C" void kernel_launch(void* const* d_in, const int* in_sizes, int n_in,
                              void* d_out, int out_size) {
    const float* x      = (const float*)d_in[0];
    const float* coords = (const float*)d_in[1];
    const float* W_app  = (const float*)d_in[2];
    const float* b_app  = (const float*)d_in[3];
    const float* W_geom = (const float*)d_in[4];
    const float* b_geom = (const float*)d_in[5];
    const float* W_aff  = (const float*)d_in[6];
    const float* b_aff  = (const float*)d_in[7];
    const float* W_c1   = (const float*)d_in[8];
    const float* b_c1   = (const float*)d_in[9];
    const float* W_m1   = (const float*)d_in[10];
    const float* b_m1   = (const float*)d_in[11];
    const float* W_c2   = (const float*)d_in[12];
    // d_in[13] = b_c2 (cancels in pairwise diff; unused)
    const float* W_f1   = (const float*)d_in[14];
    const float* b_f1   = (const float*)d_in[15];
    const float* W_f2   = (const float*)d_in[16];
    const float* b_f2   = (const float*)d_in[17];
    const int* ei  = (const int*)d_in[18];
    const int* ei2 = (const int*)d_in[19];
    const int* src = ei;
    const int* dst = ei + NE;

    float *h1p, *out1p, *h2p;
    cudaGetSymbolAddress((void**)&h1p, g_h1);
    cudaGetSymbolAddress((void**)&out1p, g_out1);
    cudaGetSymbolAddress((void**)&h2p, g_h2);

    // Second stream + events (created once, outside capture).
    static cudaStream_t sB = nullptr;
    static cudaEvent_t evFork = nullptr, evG1 = nullptr, evGa1 = nullptr, evG2 = nullptr;
    if (sB == nullptr) {
        cudaStreamCreateWithFlags(&sB, cudaStreamNonBlocking);
        cudaEventCreateWithFlags(&evFork, cudaEventDisableTiming);
        cudaEventCreateWithFlags(&evG1, cudaEventDisableTiming);
        cudaEventCreateWithFlags(&evGa1, cudaEventDisableTiming);
        cudaEventCreateWithFlags(&evG2, cudaEventDisableTiming);
    }
    cudaStream_t sA = 0;  // default (capture) stream

    // fork: sB joins the capture
    cudaEventRecord(evFork, sA);
    cudaStreamWaitEvent(sB, evFork, 0);

    // --- island 1: GEMM1 (sB) || edge/CSR prep (sA) ---
    k_gemm_tf32<0><<<dim3((NN + 127) / 128, C1 / 128), 256, 0, sB>>>(
        x, W_c1, h1p, NN, C1, DIN, nullptr);
    cudaEventRecord(evG1, sB);

    k_node_dots<<<(NN + 7) / 8, 256, 0, sA>>>(x, coords, W_app, W_geom);
    k_edge1<<<(NE + 255) / 256, 256, 0, sA>>>(src, dst, W_aff, b_app, b_geom, b_aff);
    k_scanA<<<NB, 256, 0, sA>>>();
    k_scanB<<<1, 256, 0, sA>>>();
    k_scanC<<<NB, 256, 0, sA>>>();
    k_place<<<(NE + 255) / 256, 256, 0, sA>>>(src, dst);
    k_dinv1<<<(NN + 255) / 256, 256, 0, sA>>>();

    // join: gather1 needs h1 (sB) + CSR/dinv1 (sA)
    cudaStreamWaitEvent(sA, evG1, 0);
    k_gather1<<<(NN * 32 + 255) / 256, 256, 0, sA>>>();
    cudaEventRecord(evGa1, sA);

    // --- island 2: GEMM2 (sB) || mdots->edge2->dinv2 (sA) ---
    cudaStreamWaitEvent(sB, evGa1, 0);
    k_gemm_tf32<1><<<dim3((NN + 127) / 128, C2 / 128), 256, 0, sB>>>(
        out1p, W_c2, h2p, NN, C2, C1, b_c1);
    cudaEventRecord(evG2, sB);

    k_mdots<<<(NN + 7) / 8, 256, 0, sA>>>(W_m1, b_c1);
    k_edge2<<<(NE + 255) / 256, 256, 0, sA>>>(src, dst, b_m1);
    k_dinv2<<<(NN + 255) / 256, 256, 0, sA>>>();

    // join: gather2proj needs h2 (sB) + ew2/dinv2 (sA)
    cudaStreamWaitEvent(sA, evG2, 0);
    k_gather2proj<<<256, 256, 0, sA>>>(W_f1);
    k_final<<<(NE * 16 + 255) / 256, 256, 0, sA>>>(ei2, ei2 + NE, b_f1, W_f2, b_f2,
                                                   (float*)d_out);
}

// round 17
// speedup vs baseline: 1.3479x; 1.0207x over previous
#include <cuda_runtime.h>
#include <cuda_bf16.h>
#include <math.h>
#include <stdint.h>
#include <stddef.h>

// Problem constants (fixed by the dataset)
#define NN 50000
#define NE 800000
#define DIN 512
#define C1 256
#define C2 128
#define HID 64
#define NB ((NN + 255) / 256)   // 196 scan blocks

// ---------------- scratch (device globals; no allocations allowed) ----------
__device__ float g_app_s[NN];
__device__ float g_app_d[NN];
__device__ float g_geo_s[NN];
__device__ float g_geo_d[NN];
__device__ float g_ew1[NE];
__device__ float g_deg1[NN];   // deg, then overwritten with dinv
__device__ float g_ms[NN];
__device__ float g_md[NN];
__device__ float g_ew2[NE];
__device__ float g_deg2[NN];
__device__ float g_h1[(size_t)NN * C1];
__device__ float g_out1[(size_t)NN * C1];   // pre-bias GCN1 result
__device__ float g_h2[(size_t)NN * C2];
__device__ float g_proj[(size_t)NN * HID];
// dst-CSR (rebuilt every launch; shared by both GCN layers)
__device__ int  g_cnt[NN];      // per-dst edge count (all edges)
__device__ int  g_rowptr[NN];   // exclusive prefix of g_cnt
__device__ int  g_woff[NN];     // write cursors for placement
__device__ int  g_bsum[256];    // scan block partials
__device__ int2 g_csr[NE];      // {src, edge_id} per slot

// ---------------- helpers ----------------------------------------------------
__device__ __forceinline__ float warpReduceSum(float v) {
#pragma unroll
    for (int off = 16; off > 0; off >>= 1)
        v += __shfl_down_sync(0xFFFFFFFFu, v, off);
    return v;
}

// Raw f32 bits as tf32 operand (truncation; error budget has >5x margin).
__device__ __forceinline__ uint32_t f2tf(float f) {
    return __float_as_uint(f);
}

__device__ __forceinline__ void mma_tf32(float* c, const uint32_t* a, const uint32_t* b) {
    asm volatile(
        "mma.sync.aligned.m16n8k8.row.col.f32.tf32.tf32.f32 "
        "{%0,%1,%2,%3}, {%4,%5,%6,%7}, {%8,%9}, {%0,%1,%2,%3};"
        : "+f"(c[0]), "+f"(c[1]), "+f"(c[2]), "+f"(c[3])
        : "r"(a[0]), "r"(a[1]), "r"(a[2]), "r"(a[3]), "r"(b[0]), "r"(b[1]));
}

#define CP_ASYNC16(dst, src) \
    asm volatile("cp.async.cg.shared.global [%0], [%1], 16;" :: "r"(dst), "l"(src))
#define CP_COMMIT asm volatile("cp.async.commit_group;")
template <int N>
__device__ __forceinline__ void cp_wait() {
    asm volatile("cp.async.wait_group %0;" :: "n"(N));
}

// ---------------- kernels ----------------------------------------------------

// node dots + zero degree and CSR-count accumulators (fused)
__global__ void k_node_dots(const float* __restrict__ x,
                            const float* __restrict__ coords,
                            const float* __restrict__ Wapp,
                            const float* __restrict__ Wgeom) {
    int gw = (blockIdx.x * blockDim.x + threadIdx.x) >> 5;
    int lane = threadIdx.x & 31;
    if (gw >= NN) return;
    const float4* row = (const float4*)(x + (size_t)gw * DIN);
    const float4* wa = (const float4*)Wapp;
    float s = 0.f, d = 0.f;
#pragma unroll
    for (int i = 0; i < 4; i++) {
        int idx = lane + 32 * i;
        float4 v = row[idx];
        float4 ws = wa[idx];
        float4 wd = wa[idx + 128];
        s += v.x * ws.x + v.y * ws.y + v.z * ws.z + v.w * ws.w;
        d += v.x * wd.x + v.y * wd.y + v.z * wd.z + v.w * wd.w;
    }
    s = warpReduceSum(s);
    d = warpReduceSum(d);
    if (lane == 0) {
        g_app_s[gw] = s;
        g_app_d[gw] = d;
        float4 c = ((const float4*)coords)[gw];
        g_geo_s[gw] = c.x * Wgeom[0] + c.y * Wgeom[1] + c.z * Wgeom[2] + c.w * Wgeom[3];
        g_geo_d[gw] = c.x * Wgeom[4] + c.y * Wgeom[5] + c.z * Wgeom[6] + c.w * Wgeom[7];
        g_deg1[gw] = 0.f;
        g_deg2[gw] = 0.f;
        g_cnt[gw] = 0;
    }
}

// edge weights for GCN1 + degree + CSR histogram
__global__ void k_edge1(const int* __restrict__ src, const int* __restrict__ dst,
                        const float* __restrict__ Waff,
                        const float* __restrict__ bapp,
                        const float* __restrict__ bgeom,
                        const float* __restrict__ baff) {
    int e = blockIdx.x * blockDim.x + threadIdx.x;
    if (e >= NE) return;
    int s = src[e], d = dst[e];
    float x1 = fmaxf(g_app_s[s] + g_app_d[d] + bapp[0], 0.f);
    float x2 = fmaxf(g_geo_s[s] + g_geo_d[d] + bgeom[0], 0.f);
    float ew = fmaxf(x1 * Waff[0] + x2 * Waff[1] + baff[0], 0.f);
    g_ew1[e] = ew;
    if (ew != 0.f) atomicAdd(&g_deg1[d], ew);
    atomicAdd(&g_cnt[d], 1);
}

// ---- 3-phase multi-block exclusive scan of g_cnt ----
__global__ void k_scanA() {
    __shared__ int sh[256];
    int idx = blockIdx.x * 256 + threadIdx.x;
    sh[threadIdx.x] = (idx < NN) ? g_cnt[idx] : 0;
    __syncthreads();
#pragma unroll
    for (int off = 128; off > 0; off >>= 1) {
        if (threadIdx.x < off) sh[threadIdx.x] += sh[threadIdx.x + off];
        __syncthreads();
    }
    if (threadIdx.x == 0) g_bsum[blockIdx.x] = sh[0];
}

__global__ void k_scanB() {
    __shared__ int sh[256];
    int t = threadIdx.x;
    sh[t] = (t < NB) ? g_bsum[t] : 0;
    __syncthreads();
    for (int off = 1; off < 256; off <<= 1) {
        int v = (t >= off) ? sh[t - off] : 0;
        __syncthreads();
        sh[t] += v;
        __syncthreads();
    }
    if (t < NB) g_bsum[t] = (t > 0) ? sh[t - 1] : 0;   // exclusive
}

__global__ void k_scanC() {
    __shared__ int sh[256];
    int t = threadIdx.x;
    int idx = blockIdx.x * 256 + t;
    int v = (idx < NN) ? g_cnt[idx] : 0;
    sh[t] = v;
    __syncthreads();
    for (int off = 1; off < 256; off <<= 1) {
        int u = (t >= off) ? sh[t - off] : 0;
        __syncthreads();
        sh[t] += u;
        __syncthreads();
    }
    if (idx < NN) {
        int ex = sh[t] - v + g_bsum[blockIdx.x];
        g_rowptr[idx] = ex;
        g_woff[idx] = ex;
    }
}

// place edges into CSR slots
__global__ void k_place(const int* __restrict__ src, const int* __restrict__ dst) {
    int e = blockIdx.x * blockDim.x + threadIdx.x;
    if (e >= NE) return;
    int d = dst[e];
    int pos = atomicAdd(&g_woff[d], 1);
    g_csr[pos] = make_int2(src[e], e);
}

__global__ void k_dinv1() {
    int i = blockIdx.x * blockDim.x + threadIdx.x;
    if (i < NN) g_deg1[i] = rsqrtf(g_deg1[i] + 1.0f);  // +1 self-loop; deg>=1
}

__global__ void k_dinv2() {
    int i = blockIdx.x * blockDim.x + threadIdx.x;
    if (i < NN) g_deg2[i] = rsqrtf(g_deg2[i] + 1.0f);
}

// ---------------- TF32 tensor-core GEMM (3-stage cp.async pipeline) ----------
// C[M,N] = A[M,K] @ B[K,N], row-major. Block tile 128x128x16, 8 warps,
// warp tile 32x64 via m16n8k8. 3 smem stages, prefetch depth 2, ONE
// __syncthreads per k-tile. Dynamic smem (56832 B) via FuncSetAttribute.
// MODE bit0: apply relu(a + biasA[k]) to A fragments.
#define GA_BM 128
#define GA_BK 16
#define GA_AS_STRIDE 20
#define GA_BS_STRIDE 136
#define GA_AS_FLOATS (GA_BM * GA_AS_STRIDE)   // 2560
#define GA_BS_FLOATS (GA_BK * GA_BS_STRIDE)   // 2176
#define GA_SMEM_BYTES (3 * (GA_AS_FLOATS + GA_BS_FLOATS) * 4)  // 56832

template <int MODE>
__global__ __launch_bounds__(256) void k_gemm_tf32(
    const float* __restrict__ A, const float* __restrict__ B,
    float* __restrict__ C, int M, int N, int K,
    const float* __restrict__ biasA) {
    extern __shared__ float dynsmem[];
    float* AsBase = dynsmem;                       // 3 x 2560
    float* BsBase = dynsmem + 3 * GA_AS_FLOATS;    // 3 x 2176

    const int tid = threadIdx.x;
    const int lane = tid & 31;
    const int wid = tid >> 5;
    const int wm = wid & 3;
    const int wn = wid >> 2;
    const int grp = lane >> 2;
    const int qid = lane & 3;

    const int row0 = blockIdx.x * GA_BM;
    const int col0 = blockIdx.y * 128;

    const int ar0 = tid >> 2;
    const int ac = (tid & 3) * 4;
    const int br0 = tid >> 5;
    const int bc = (tid & 31) * 4;

    const int arow_g0 = min(row0 + ar0, M - 1);
    const int arow_g1 = min(row0 + ar0 + 64, M - 1);

    float acc[2][8][4];
#pragma unroll
    for (int mt = 0; mt < 2; mt++)
#pragma unroll
        for (int nt = 0; nt < 8; nt++)
#pragma unroll
            for (int i = 0; i < 4; i++) acc[mt][nt][i] = 0.f;

    auto load_tile = [&](int stg, int k0) {
        float* as = AsBase + stg * GA_AS_FLOATS;
        float* bs = BsBase + stg * GA_BS_FLOATS;
        uint32_t a_s0 = (uint32_t)__cvta_generic_to_shared(&as[ar0 * GA_AS_STRIDE + ac]);
        uint32_t a_s1 = (uint32_t)__cvta_generic_to_shared(&as[(ar0 + 64) * GA_AS_STRIDE + ac]);
        CP_ASYNC16(a_s0, A + (size_t)arow_g0 * K + k0 + ac);
        CP_ASYNC16(a_s1, A + (size_t)arow_g1 * K + k0 + ac);
        uint32_t b_s0 = (uint32_t)__cvta_generic_to_shared(&bs[br0 * GA_BS_STRIDE + bc]);
        uint32_t b_s1 = (uint32_t)__cvta_generic_to_shared(&bs[(br0 + 8) * GA_BS_STRIDE + bc]);
        CP_ASYNC16(b_s0, B + (size_t)(k0 + br0) * N + col0 + bc);
        CP_ASYNC16(b_s1, B + (size_t)(k0 + br0 + 8) * N + col0 + bc);
    };

    const int ntiles = K / GA_BK;   // >= 16 for both call sites
    load_tile(0, 0);
    CP_COMMIT;
    load_tile(1, GA_BK);
    CP_COMMIT;

    const int arow_base = wm * 32 + grp;
    const int bcol_base = wn * 64 + grp;

    int stg = 0;
    for (int t = 0; t < ntiles; t++) {
        cp_wait<1>();          // tile t's group complete (t+1's may be in flight)
        __syncthreads();       // data visible to all; all done reading stage being refilled
        if (t + 2 < ntiles) load_tile((t + 2) % 3, (t + 2) * GA_BK);
        CP_COMMIT;             // exactly one group per iteration (may be empty)

        const int k0 = t * GA_BK;
        const float* as = AsBase + stg * GA_AS_FLOATS;
        const float* bs = BsBase + stg * GA_BS_FLOATS;
#pragma unroll
        for (int ks = 0; ks < 2; ks++) {
            const int kk = ks * 8 + qid;
            float ab0 = 0.f, ab1 = 0.f;
            if (MODE & 1) {
                ab0 = biasA[k0 + kk];
                ab1 = biasA[k0 + kk + 4];
            }
            uint32_t a[2][4];
#pragma unroll
            for (int mt = 0; mt < 2; mt++) {
                const float* ap = as + (arow_base + mt * 16) * GA_AS_STRIDE + kk;
                float v0 = ap[0];
                float v1 = ap[8 * GA_AS_STRIDE];
                float v2 = ap[4];
                float v3 = ap[8 * GA_AS_STRIDE + 4];
                if (MODE & 1) {
                    v0 = fmaxf(v0 + ab0, 0.f);
                    v1 = fmaxf(v1 + ab0, 0.f);
                    v2 = fmaxf(v2 + ab1, 0.f);
                    v3 = fmaxf(v3 + ab1, 0.f);
                }
                a[mt][0] = f2tf(v0);
                a[mt][1] = f2tf(v1);
                a[mt][2] = f2tf(v2);
                a[mt][3] = f2tf(v3);
            }
            const float* bp = bs + kk * GA_BS_STRIDE + bcol_base;
#pragma unroll
            for (int nt = 0; nt < 8; nt++) {
                uint32_t b[2];
                b[0] = f2tf(bp[nt * 8]);
                b[1] = f2tf(bp[4 * GA_BS_STRIDE + nt * 8]);
                mma_tf32(acc[0][nt], a[0], b);
                mma_tf32(acc[1][nt], a[1], b);
            }
        }
        stg = (stg + 1) % 3;
    }

#pragma unroll
    for (int mt = 0; mt < 2; mt++) {
        int r = row0 + wm * 32 + mt * 16 + grp;
#pragma unroll
        for (int nt = 0; nt < 8; nt++) {
            int c = col0 + wn * 64 + nt * 8 + qid * 2;
            if (r < M)
                *(float2*)(C + (size_t)r * N + c) =
                    make_float2(acc[mt][nt][0], acc[mt][nt][1]);
            if (r + 8 < M)
                *(float2*)(C + (size_t)(r + 8) * N + c) =
                    make_float2(acc[mt][nt][2], acc[mt][nt][3]);
        }
    }
}

// GCN1 aggregation: gather per dst node (warp per node). out1[d] =
// dinv1[d]^2*h1[d] + sum_e coef_e * h1[src_e].  256-dim: 2 float4/lane.
__global__ void k_gather1() {
    int node = (blockIdx.x * blockDim.x + threadIdx.x) >> 5;
    if (node >= NN) return;
    int lane = threadIdx.x & 31;
    int start = g_rowptr[node];
    int cnt = g_cnt[node];
    float di = g_deg1[node];
    const float4* hd = (const float4*)(g_h1 + (size_t)node * C1);
    float self = di * di;
    float4 v0 = hd[lane], v1 = hd[lane + 32];
    float4 acc0 = make_float4(self * v0.x, self * v0.y, self * v0.z, self * v0.w);
    float4 acc1 = make_float4(self * v1.x, self * v1.y, self * v1.z, self * v1.w);
    for (int i = 0; i < cnt; i++) {
        int2 se = g_csr[start + i];
        float ew = g_ew1[se.y];
        if (ew == 0.f) continue;
        float coef = g_deg1[se.x] * ew * di;
        const float4* hs = (const float4*)(g_h1 + (size_t)se.x * C1);
        float4 a = hs[lane], b = hs[lane + 32];
        acc0.x += coef * a.x; acc0.y += coef * a.y;
        acc0.z += coef * a.z; acc0.w += coef * a.w;
        acc1.x += coef * b.x; acc1.y += coef * b.y;
        acc1.z += coef * b.z; acc1.w += coef * b.w;
    }
    float4* od = (float4*)(g_out1 + (size_t)node * C1);
    od[lane] = acc0;
    od[lane + 32] = acc1;
}

// GCN2 aggregation fused with proj: out2 row stays in smem, proj = row @ W_f1.
__global__ __launch_bounds__(256) void k_gather2proj(const float* __restrict__ Wf1) {
    __shared__ float W1s[C2 * HID];     // 32 KB
    __shared__ float rows[8][C2];       // 4 KB, one row per warp
    for (int i = threadIdx.x; i < C2 * HID; i += blockDim.x) W1s[i] = Wf1[i];
    __syncthreads();
    const int lane = threadIdx.x & 31;
    const int wrp = threadIdx.x >> 5;
    const int gw0 = (blockIdx.x * blockDim.x + threadIdx.x) >> 5;
    const int nwarps = (gridDim.x * blockDim.x) >> 5;
    float* row = rows[wrp];
    for (int node = gw0; node < NN; node += nwarps) {
        int start = g_rowptr[node];
        int cnt = g_cnt[node];
        float di = g_deg2[node];
        const float4* hd = (const float4*)(g_h2 + (size_t)node * C2);
        float self = di * di;
        float4 v0 = hd[lane];
        float4 acc = make_float4(self * v0.x, self * v0.y, self * v0.z, self * v0.w);
        for (int i = 0; i < cnt; i++) {
            int2 se = g_csr[start + i];
            float ew = g_ew2[se.y];
            if (ew == 0.f) continue;
            float coef = g_deg2[se.x] * ew * di;
            const float4* hs = (const float4*)(g_h2 + (size_t)se.x * C2);
            float4 a = hs[lane];
            acc.x += coef * a.x; acc.y += coef * a.y;
            acc.z += coef * a.z; acc.w += coef * a.w;
        }
        ((float4*)row)[lane] = acc;
        __syncwarp();
        float p0 = 0.f, p1 = 0.f;
#pragma unroll 8
        for (int k = 0; k < C2; k++) {
            float rv = row[k];
            p0 = fmaf(rv, W1s[k * HID + lane], p0);
            p1 = fmaf(rv, W1s[k * HID + lane + 32], p1);
        }
        g_proj[(size_t)node * HID + lane] = p0;
        g_proj[(size_t)node * HID + lane + 32] = p1;
        __syncwarp();
    }
}

// m_s / m_d dots over relu(out1 + b_c1), warp per node (bias+relu inline)
__global__ void k_mdots(const float* __restrict__ Wm1, const float* __restrict__ bc1) {
    int gw = (blockIdx.x * blockDim.x + threadIdx.x) >> 5;
    int lane = threadIdx.x & 31;
    if (gw >= NN) return;
    const float4* row = (const float4*)(g_out1 + (size_t)gw * C1);
    const float4* wm = (const float4*)Wm1;
    const float4* bb = (const float4*)bc1;
    float s = 0.f, d = 0.f;
#pragma unroll
    for (int i = 0; i < 2; i++) {
        int idx = lane + 32 * i;
        float4 v = row[idx];
        float4 b = bb[idx];
        v.x = fmaxf(v.x + b.x, 0.f);
        v.y = fmaxf(v.y + b.y, 0.f);
        v.z = fmaxf(v.z + b.z, 0.f);
        v.w = fmaxf(v.w + b.w, 0.f);
        float4 ws = wm[idx];
        float4 wd = wm[idx + 64];
        s += v.x * ws.x + v.y * ws.y + v.z * ws.z + v.w * ws.w;
        d += v.x * wd.x + v.y * wd.y + v.z * wd.z + v.w * wd.w;
    }
    s = warpReduceSum(s);
    d = warpReduceSum(d);
    if (lane == 0) { g_ms[gw] = s; g_md[gw] = d; }
}

__global__ void k_edge2(const int* __restrict__ src, const int* __restrict__ dst,
                        const float* __restrict__ bm1) {
    int e = blockIdx.x * blockDim.x + threadIdx.x;
    if (e >= NE) return;
    int s = src[e], d = dst[e];
    float ea = fmaxf(g_ms[s] + g_md[d] + bm1[0], 0.f);
    g_ew2[e] = ea;
    if (ea != 0.f) atomicAdd(&g_deg2[d], ea);
}

// final: sigmoid( relu(proj[a]-proj[b]+b_f1) @ W_f2 + b_f2 )
// half-warp (16 lanes) per edge, float4 loads
__global__ void k_final(const int* __restrict__ ea, const int* __restrict__ eb,
                        const float* __restrict__ bf1, const float* __restrict__ Wf2,
                        const float* __restrict__ bf2, float* __restrict__ out) {
    int t = blockIdx.x * blockDim.x + threadIdx.x;
    int e = t >> 4;
    if (e >= NE) return;
    int l16 = t & 15;
    int a = ea[e], b = eb[e];
    float4 va = ((const float4*)(g_proj + (size_t)a * HID))[l16];
    float4 vb = ((const float4*)(g_proj + (size_t)b * HID))[l16];
    float4 bb = ((const float4*)bf1)[l16];
    float4 w  = ((const float4*)Wf2)[l16];
    float acc = fmaxf(va.x - vb.x + bb.x, 0.f) * w.x
              + fmaxf(va.y - vb.y + bb.y, 0.f) * w.y
              + fmaxf(va.z - vb.z + bb.z, 0.f) * w.z
              + fmaxf(va.w - vb.w + bb.w, 0.f) * w.w;
#pragma unroll
    for (int off = 8; off > 0; off >>= 1)
        acc += __shfl_down_sync(0xFFFFFFFFu, acc, off, 16);
    if (l16 == 0) {
        float z = acc + bf2[0];
        out[e] = 1.f / (1.f + expf(-z));
    }
}

// ---------------- launcher ---------------------------------------------------
extern "C" void kernel_launch(void* const* d_in, const int* in_sizes, int n_in,
                              void* d_out, int out_size) {
    const float* x      = (const float*)d_in[0];
    const float* coords = (const float*)d_in[1];
    const float* W_app  = (const float*)d_in[2];
    const float* b_app  = (const float*)d_in[3];
    const float* W_geom = (const float*)d_in[4];
    const float* b_geom = (const float*)d_in[5];
    const float* W_aff  = (const float*)d_in[6];
    const float* b_aff  = (const float*)d_in[7];
    const float* W_c1   = (const float*)d_in[8];
    const float* b_c1   = (const float*)d_in[9];
    const float* W_m1   = (const float*)d_in[10];
    const float* b_m1   = (const float*)d_in[11];
    const float* W_c2   = (const float*)d_in[12];
    // d_in[13] = b_c2 (cancels in pairwise diff; unused)
    const float* W_f1   = (const float*)d_in[14];
    const float* b_f1   = (const float*)d_in[15];
    const float* W_f2   = (const float*)d_in[16];
    const float* b_f2   = (const float*)d_in[17];
    const int* ei  = (const int*)d_in[18];
    const int* ei2 = (const int*)d_in[19];
    const int* src = ei;
    const int* dst = ei + NE;

    float *h1p, *out1p, *h2p;
    cudaGetSymbolAddress((void**)&h1p, g_h1);
    cudaGetSymbolAddress((void**)&out1p, g_out1);
    cudaGetSymbolAddress((void**)&h2p, g_h2);

    // Second stream + events + GEMM smem attribute (once, outside capture).
    static cudaStream_t sB = nullptr;
    static cudaEvent_t evFork = nullptr, evG1 = nullptr, evGa1 = nullptr, evG2 = nullptr;
    if (sB == nullptr) {
        cudaStreamCreateWithFlags(&sB, cudaStreamNonBlocking);
        cudaEventCreateWithFlags(&evFork, cudaEventDisableTiming);
        cudaEventCreateWithFlags(&evG1, cudaEventDisableTiming);
        cudaEventCreateWithFlags(&evGa1, cudaEventDisableTiming);
        cudaEventCreateWithFlags(&evG2, cudaEventDisableTiming);
        cudaFuncSetAttribute(k_gemm_tf32<0>,
                             cudaFuncAttributeMaxDynamicSharedMemorySize, GA_SMEM_BYTES);
        cudaFuncSetAttribute(k_gemm_tf32<1>,
                             cudaFuncAttributeMaxDynamicSharedMemorySize, GA_SMEM_BYTES);
    }
    cudaStream_t sA = 0;  // default (capture) stream

    // fork: sB joins the capture
    cudaEventRecord(evFork, sA);
    cudaStreamWaitEvent(sB, evFork, 0);

    // --- island 1: GEMM1 (sB) || edge/CSR prep (sA) ---
    k_gemm_tf32<0><<<dim3((NN + 127) / 128, C1 / 128), 256, GA_SMEM_BYTES, sB>>>(
        x, W_c1, h1p, NN, C1, DIN, nullptr);
    cudaEventRecord(evG1, sB);

    k_node_dots<<<(NN + 7) / 8, 256, 0, sA>>>(x, coords, W_app, W_geom);
    k_edge1<<<(NE + 255) / 256, 256, 0, sA>>>(src, dst, W_aff, b_app, b_geom, b_aff);
    k_scanA<<<NB, 256, 0, sA>>>();
    k_scanB<<<1, 256, 0, sA>>>();
    k_scanC<<<NB, 256, 0, sA>>>();
    k_place<<<(NE + 255) / 256, 256, 0, sA>>>(src, dst);
    k_dinv1<<<(NN + 255) / 256, 256, 0, sA>>>();

    // join: gather1 needs h1 (sB) + CSR/dinv1 (sA)
    cudaStreamWaitEvent(sA, evG1, 0);
    k_gather1<<<(NN * 32 + 255) / 256, 256, 0, sA>>>();
    cudaEventRecord(evGa1, sA);

    // --- island 2: GEMM2 (sB) || mdots->edge2->dinv2 (sA) ---
    cudaStreamWaitEvent(sB, evGa1, 0);
    k_gemm_tf32<1><<<dim3((NN + 127) / 128, C2 / 128), 256, GA_SMEM_BYTES, sB>>>(
        out1p, W_c2, h2p, NN, C2, C1, b_c1);
    cudaEventRecord(evG2, sB);

    k_mdots<<<(NN + 7) / 8, 256, 0, sA>>>(W_m1, b_c1);
    k_edge2<<<(NE + 255) / 256, 256, 0, sA>>>(src, dst, b_m1);
    k_dinv2<<<(NN + 255) / 256, 256, 0, sA>>>();

    // join: gather2proj needs h2 (sB) + ew2/dinv2 (sA)
    cudaStreamWaitEvent(sA, evG2, 0);
    k_gather2proj<<<256, 256, 0, sA>>>(W_f1);
    k_final<<<(NE * 16 + 255) / 256, 256, 0, sA>>>(ei2, ei2 + NE, b_f1, W_f2, b_f2,
                                                   (float*)d_out);
}